// round 3
// baseline (speedup 1.0000x reference)
#include <cuda_runtime.h>
#include <math.h>
#include <stdint.h>

#define Tn 64
#define Bn 64
#define Sn 512
#define An 16
#define Rn 64
#define Hn 32
#define EPSF 1e-6f

#define ISL 4            // i-slices per (j-tile, k) in the step GEMM
#define NP  (An*ISL)     // 64 partial slabs

// ---------------- scratch (device globals; no allocation) ----------------
__device__ __align__(16) float g_trans[(size_t)An*Sn*Sn];   // 16.8 MB
__device__ float g_G[Sn*Sn];                                 // 1 MB
__device__ float g_p[An*Sn];
__device__ float g_taupdf[Hn];
__device__ float g_alpha_a[(size_t)Tn*Bn*An];
__device__ __align__(16) float g_belT[Sn*Bn];                // belief, transposed [j][n]
__device__ __align__(16) float g_part[(size_t)NP*Bn*Sn];     // 8 MB partials

// ---------------- precompute: v_norm and p[k][i] = u[i].v_hat[k] ----------------
__global__ void k_pv(const float* __restrict__ u, const float* __restrict__ v) {
    int k = blockIdx.x;
    int t = threadIdx.x;  // 64 threads
    __shared__ float vn[Rn];
    __shared__ float sb[64];
    float x = v[k*Rn + t];
    sb[t] = x * x;
    __syncthreads();
    for (int s = 32; s > 0; s >>= 1) { if (t < s) sb[t] += sb[t+s]; __syncthreads(); }
    vn[t] = x * rsqrtf(sb[0]);
    __syncthreads();
    for (int i = t; i < Sn; i += 64) {
        float s = 0.f;
        #pragma unroll
        for (int r = 0; r < Rn; r++) s += u[i*Rn + r] * vn[r];
        g_p[k*Sn + i] = s;
    }
}

// ---------------- precompute: G[i][j] = u[i].u[j] ----------------
__global__ void k_gram(const float* __restrict__ u) {
    int i = blockIdx.x;
    int tid = threadIdx.x;  // 128
    __shared__ float ui[Rn];
    if (tid < Rn) ui[tid] = u[i*Rn + tid];
    __syncthreads();
    for (int j = tid; j < Sn; j += 128) {
        float s = 0.f;
        #pragma unroll
        for (int r = 0; r < Rn; r++) s += u[j*Rn + r] * ui[r];
        g_G[i*Sn + j] = s;
    }
}

// ---------------- precompute: transition rows (softmax over j) ----------------
__global__ void k_trans() {
    int i = blockIdx.x, k = blockIdx.y;
    int j = threadIdx.x;  // 512
    __shared__ float red[512];
    float pki = g_p[k*Sn + i];
    float w = g_G[i*Sn + j] - 2.f * pki * g_p[k*Sn + j];
    red[j] = w; __syncthreads();
    for (int s = 256; s > 0; s >>= 1) { if (j < s) red[j] = fmaxf(red[j], red[j+s]); __syncthreads(); }
    float m = red[0]; __syncthreads();
    float e = expf(w - m);
    red[j] = e; __syncthreads();
    for (int s = 256; s > 0; s >>= 1) { if (j < s) red[j] += red[j+s]; __syncthreads(); }
    g_trans[((size_t)(k*Sn + i))*Sn + j] = e * (1.f / red[0]);
}

// ---------------- precompute: normalized Poisson pdf over horizon ----------------
__global__ void k_taupdf(const float* __restrict__ tau) {
    int t = threadIdx.x;  // 32
    float rate = log1pf(expf(tau[0]));   // softplus
    float kk = (float)(t + 1);
    float lp = kk * logf(rate) - rate - lgammaf(kk + 1.f);
    float p = expf(lp);
    float s = p;
    #pragma unroll
    for (int o = 16; o > 0; o >>= 1) s += __shfl_xor_sync(0xffffffffu, s, o);
    g_taupdf[t] = p / s;
}

// ---------------- precompute: alpha_a = softmax(logp_u) over A ----------------
__global__ void k_alpha_a(const float* __restrict__ logp_u) {
    int idx = blockIdx.x * blockDim.x + threadIdx.x;
    if (idx >= Tn*Bn) return;
    const float* r = logp_u + (size_t)idx*An;
    float m = -1e30f;
    #pragma unroll
    for (int k = 0; k < An; k++) m = fmaxf(m, r[k]);
    float e[An]; float s = 0.f;
    #pragma unroll
    for (int k = 0; k < An; k++) { e[k] = expf(r[k] - m); s += e[k]; }
    float inv = 1.f / s;
    #pragma unroll
    for (int k = 0; k < An; k++) g_alpha_a[(size_t)idx*An + k] = e[k] * inv;
}

// ---------------- init belief (transposed) ----------------
__global__ void k_init_bel(const float* __restrict__ b) {
    int n = blockIdx.x, j = threadIdx.x;  // (Bn, Sn)
    g_belT[j*Bn + n] = b[n*Sn + j];
}

// ---------------- scan step: partial GEMM s_next += c[n,(k,i)] * T[(k,i),j] ----------------
#define TJ 128
#define CH 32
#define ILEN (Sn/ISL)   // 128
__global__ void k_step_gemm(int t) {
    int tid = threadIdx.x;      // 256
    int tn = tid & 15;          // 16 n-groups of 4
    int tj = tid >> 4;          // 16 j-groups of 8
    int j0 = blockIdx.x * TJ;
    int k  = blockIdx.y;
    int i0 = blockIdx.z * ILEN;

    __shared__ float ash[Bn];
    __shared__ __align__(16) float csh[CH][Bn];   // c[n] per i-row
    __shared__ __align__(16) float Tsh[CH][TJ];

    if (tid < Bn) ash[tid] = g_alpha_a[((size_t)t*Bn + tid)*An + k];

    float acc[4][8];
    #pragma unroll
    for (int a = 0; a < 4; a++)
        #pragma unroll
        for (int b = 0; b < 8; b++) acc[a][b] = 0.f;
    __syncthreads();

    for (int ic = 0; ic < ILEN; ic += CH) {
        int ib = i0 + ic;
        #pragma unroll
        for (int q = 0; q < (CH*Bn)/256; q++) {           // 8
            int e = tid + q*256; int il = e >> 6, n = e & 63;
            csh[il][n] = ash[n] * g_belT[(ib + il)*Bn + n];
        }
        #pragma unroll
        for (int q = 0; q < (CH*TJ)/256; q++) {           // 16
            int e = tid + q*256; int il = e >> 7, jj = e & 127;
            Tsh[il][jj] = g_trans[((size_t)(k*Sn + ib + il))*Sn + j0 + jj];
        }
        __syncthreads();
        for (int il = 0; il < CH; il++) {
            float4 cv = *reinterpret_cast<const float4*>(&csh[il][tn*4]);
            float4 t0 = *reinterpret_cast<const float4*>(&Tsh[il][tj*8]);
            float4 t1 = *reinterpret_cast<const float4*>(&Tsh[il][tj*8 + 4]);
            float cva[4] = {cv.x, cv.y, cv.z, cv.w};
            float tv[8]  = {t0.x, t0.y, t0.z, t0.w, t1.x, t1.y, t1.z, t1.w};
            #pragma unroll
            for (int a = 0; a < 4; a++)
                #pragma unroll
                for (int b = 0; b < 8; b++)
                    acc[a][b] = fmaf(cva[a], tv[b], acc[a][b]);
        }
        __syncthreads();
    }

    int p = k*ISL + blockIdx.z;
    #pragma unroll
    for (int a = 0; a < 4; a++) {
        int n = tn*4 + a;
        float* op = &g_part[((size_t)p*Bn + n)*Sn + j0 + tj*8];
        *reinterpret_cast<float4*>(op)     = make_float4(acc[a][0], acc[a][1], acc[a][2], acc[a][3]);
        *reinterpret_cast<float4*>(op + 4) = make_float4(acc[a][4], acc[a][5], acc[a][6], acc[a][7]);
    }
}

// ---------------- scan step: reduce partials, log + obs, softmax -> b_post ----------------
__global__ void k_step_post(int t, const float* __restrict__ logp_o, float* __restrict__ out_b) {
    int n = blockIdx.x, j = threadIdx.x;  // (Bn, Sn)
    float s = 0.f;
    #pragma unroll
    for (int p = 0; p < NP; p++) s += g_part[((size_t)p*Bn + n)*Sn + j];
    float val = logf(s + EPSF) + logp_o[((size_t)t*Bn + n)*Sn + j];
    __shared__ float red[512];
    red[j] = val; __syncthreads();
    for (int ss = 256; ss > 0; ss >>= 1) { if (j < ss) red[j] = fmaxf(red[j], red[j+ss]); __syncthreads(); }
    float m = red[0]; __syncthreads();
    float e = expf(val - m);
    red[j] = e; __syncthreads();
    for (int ss = 256; ss > 0; ss >>= 1) { if (j < ss) red[j] += red[j+ss]; __syncthreads(); }
    float bp = e / red[0];
    out_b[((size_t)t*Bn + n)*Sn + j] = bp;
    g_belT[j*Bn + n] = bp;
}

// ---------------- post-scan plan: logits, softmax over A, tau-weighted sum over H ----------------
__global__ void k_plan(const float* __restrict__ value,
                       const float* __restrict__ alpha_b,
                       float* __restrict__ out_pi) {
    int n = blockIdx.x, h = blockIdx.y;
    int tid = threadIdx.x;        // 256
    int tk = tid & 15;            // k
    int tg = tid >> 4;            // t-group of 4

    __shared__ float Vsh[32][17];
    __shared__ float Bsh[64][33];
    __shared__ float Lsh[64][17];

    float acc[4] = {0.f, 0.f, 0.f, 0.f};
    const float* vbase = value + ((size_t)(h*Bn + n))*An*Sn;   // + k*Sn + i
    const float* bbase = alpha_b + (size_t)n*Sn;               // + t*Bn*Sn + i

    for (int i0 = 0; i0 < Sn; i0 += 32) {
        #pragma unroll
        for (int q = 0; q < 2; q++) {
            int e = tid + q*256; int ii = e & 31, kk = e >> 5;
            Vsh[ii][kk] = vbase[(size_t)kk*Sn + i0 + ii];
        }
        #pragma unroll
        for (int q = 0; q < 8; q++) {
            int e = tid + q*256; int ii = e & 31, tt = e >> 5;
            Bsh[tt][ii] = bbase[(size_t)tt*Bn*Sn + i0 + ii];
        }
        __syncthreads();
        for (int ii = 0; ii < 32; ii++) {
            float vv = Vsh[ii][tk];
            #pragma unroll
            for (int a = 0; a < 4; a++)
                acc[a] = fmaf(Bsh[tg*4 + a][ii], vv, acc[a]);
        }
        __syncthreads();
    }

    #pragma unroll
    for (int a = 0; a < 4; a++) Lsh[tg*4 + a][tk] = acc[a];
    __syncthreads();

    if (tid < 64) {
        int t = tid;
        float m = -1e30f;
        #pragma unroll
        for (int k = 0; k < An; k++) m = fmaxf(m, Lsh[t][k]);
        float e[An]; float ssum = 0.f;
        #pragma unroll
        for (int k = 0; k < An; k++) { e[k] = expf(Lsh[t][k] - m); ssum += e[k]; }
        float w = g_taupdf[h] / ssum;
        #pragma unroll
        for (int k = 0; k < An; k++)
            atomicAdd(&out_pi[((size_t)t*Bn + n)*An + k], e[k] * w);
    }
}

// ---------------- launch ----------------
extern "C" void kernel_launch(void* const* d_in, const int* in_sizes, int n_in,
                              void* d_out, int out_size) {
    const float* logp_o = (const float*)d_in[0];
    const float* logp_u = (const float*)d_in[1];
    const float* value  = (const float*)d_in[2];
    const float* b      = (const float*)d_in[3];
    const float* u      = (const float*)d_in[4];
    const float* v      = (const float*)d_in[5];
    const float* tau    = (const float*)d_in[6];

    float* out    = (float*)d_out;
    float* out_b  = out;                       // [T,B,S]
    float* out_pi = out + (size_t)Tn*Bn*Sn;    // [T,B,A]

    k_pv<<<An, 64>>>(u, v);
    k_gram<<<Sn, 128>>>(u);
    k_trans<<<dim3(Sn, An), 512>>>();
    k_taupdf<<<1, 32>>>(tau);
    k_alpha_a<<<(Tn*Bn + 127)/128, 128>>>(logp_u);
    k_init_bel<<<Bn, Sn>>>(b);

    for (int t = 0; t < Tn; t++) {
        k_step_gemm<<<dim3(Sn/TJ, An, ISL), 256>>>(t);
        k_step_post<<<Bn, Sn>>>(t, logp_o, out_b);
    }

    cudaMemsetAsync(out_pi, 0, sizeof(float)*(size_t)Tn*Bn*An);
    k_plan<<<dim3(Bn, Hn), 256>>>(value, out_b, out_pi);
}

// round 4
// speedup vs baseline: 1.4554x; 1.4554x over previous
#include <cuda_runtime.h>
#include <math.h>
#include <stdint.h>

#define Tn 64
#define Bn 64
#define Sn 512
#define An 16
#define Rn 64
#define Hn 32
#define EPSF 1e-6f

#define ISL 4            // i-slices per (j-tile, k) in the step GEMM
#define NP  (An*ISL)     // 64 partial slabs
#define TJ 128
#define CH 32
#define ILEN (Sn/ISL)    // 128
#define NUNITS 256       // persistent CTAs = 4 jt * 16 k * 4 isl

// ---------------- scratch (device globals; no allocation) ----------------
__device__ __align__(16) float g_trans[(size_t)An*Sn*Sn];   // 16.8 MB
__device__ float g_G[Sn*Sn];                                 // 1 MB
__device__ float g_p[An*Sn];
__device__ float g_taupdf[Hn];
__device__ float g_alpha_a[(size_t)Tn*Bn*An];
__device__ __align__(16) float g_belT[Sn*Bn];                // belief, transposed [j][n]
__device__ __align__(16) float g_part[(size_t)NP*Bn*Sn];     // 8 MB partials

// grid barrier state (count returns to 0 after each barrier; gen grows forever,
// so state is valid across graph replays)
__device__ int          g_bar_count;
__device__ volatile int g_bar_gen;

// ---------------- precompute: v_norm and p[k][i] = u[i].v_hat[k] ----------------
__global__ void k_pv(const float* __restrict__ u, const float* __restrict__ v) {
    int k = blockIdx.x;
    int t = threadIdx.x;  // 64 threads
    __shared__ float vn[Rn];
    __shared__ float sb[64];
    float x = v[k*Rn + t];
    sb[t] = x * x;
    __syncthreads();
    for (int s = 32; s > 0; s >>= 1) { if (t < s) sb[t] += sb[t+s]; __syncthreads(); }
    vn[t] = x * rsqrtf(sb[0]);
    __syncthreads();
    for (int i = t; i < Sn; i += 64) {
        float s = 0.f;
        #pragma unroll
        for (int r = 0; r < Rn; r++) s += u[i*Rn + r] * vn[r];
        g_p[k*Sn + i] = s;
    }
}

// ---------------- precompute: G[i][j] = u[i].u[j] ----------------
__global__ void k_gram(const float* __restrict__ u) {
    int i = blockIdx.x;
    int tid = threadIdx.x;  // 128
    __shared__ float ui[Rn];
    if (tid < Rn) ui[tid] = u[i*Rn + tid];
    __syncthreads();
    for (int j = tid; j < Sn; j += 128) {
        float s = 0.f;
        #pragma unroll
        for (int r = 0; r < Rn; r++) s += u[j*Rn + r] * ui[r];
        g_G[i*Sn + j] = s;
    }
}

// ---------------- precompute: transition rows (softmax over j) ----------------
__global__ void k_trans() {
    int i = blockIdx.x, k = blockIdx.y;
    int j = threadIdx.x;  // 512
    __shared__ float red[512];
    float pki = g_p[k*Sn + i];
    float w = g_G[i*Sn + j] - 2.f * pki * g_p[k*Sn + j];
    red[j] = w; __syncthreads();
    for (int s = 256; s > 0; s >>= 1) { if (j < s) red[j] = fmaxf(red[j], red[j+s]); __syncthreads(); }
    float m = red[0]; __syncthreads();
    float e = expf(w - m);
    red[j] = e; __syncthreads();
    for (int s = 256; s > 0; s >>= 1) { if (j < s) red[j] += red[j+s]; __syncthreads(); }
    g_trans[((size_t)(k*Sn + i))*Sn + j] = e * (1.f / red[0]);
}

// ---------------- precompute: normalized Poisson pdf over horizon ----------------
__global__ void k_taupdf(const float* __restrict__ tau) {
    int t = threadIdx.x;  // 32
    float rate = log1pf(expf(tau[0]));   // softplus
    float kk = (float)(t + 1);
    float lp = kk * logf(rate) - rate - lgammaf(kk + 1.f);
    float p = expf(lp);
    float s = p;
    #pragma unroll
    for (int o = 16; o > 0; o >>= 1) s += __shfl_xor_sync(0xffffffffu, s, o);
    g_taupdf[t] = p / s;
}

// ---------------- precompute: alpha_a = softmax(logp_u) over A ----------------
__global__ void k_alpha_a(const float* __restrict__ logp_u) {
    int idx = blockIdx.x * blockDim.x + threadIdx.x;
    if (idx >= Tn*Bn) return;
    const float* r = logp_u + (size_t)idx*An;
    float m = -1e30f;
    #pragma unroll
    for (int k = 0; k < An; k++) m = fmaxf(m, r[k]);
    float e[An]; float s = 0.f;
    #pragma unroll
    for (int k = 0; k < An; k++) { e[k] = expf(r[k] - m); s += e[k]; }
    float inv = 1.f / s;
    #pragma unroll
    for (int k = 0; k < An; k++) g_alpha_a[(size_t)idx*An + k] = e[k] * inv;
}

// ---------------- init belief (transposed) ----------------
__global__ void k_init_bel(const float* __restrict__ b) {
    int n = blockIdx.x, j = threadIdx.x;  // (Bn, Sn)
    g_belT[j*Bn + n] = b[n*Sn + j];
}

// ---------------- grid-wide barrier (all NUNITS CTAs co-resident) ----------------
__device__ __forceinline__ void grid_sync_dev() {
    __syncthreads();
    if (threadIdx.x == 0) {
        int old = g_bar_gen;           // read BEFORE arrive (all CTAs agree on this value)
        __threadfence();               // release: stcg/partials visible before arrival
        int t = atomicAdd(&g_bar_count, 1);
        if (t == NUNITS - 1) {
            g_bar_count = 0;           // reset before releasing (safe: everyone else spins)
            __threadfence();
            g_bar_gen = old + 1;
        } else {
            while (g_bar_gen == old) __nanosleep(64);
        }
    }
    __syncthreads();
    __threadfence();                   // acquire side
}

// ---------------- fused persistent scan: 64 steps of GEMM + post ----------------
__global__ void __launch_bounds__(256, 2)
k_scan(const float* __restrict__ logp_o, float* __restrict__ out_b) {
    int tid  = threadIdx.x;            // 256
    int unit = blockIdx.x;             // 0..255
    int jt   = unit & 3;
    int kk   = (unit >> 2) & 15;
    int isl  = unit >> 6;
    int j0   = jt * TJ;
    int i0   = isl * ILEN;
    int tn   = tid & 15;               // 16 n-groups of 4
    int tj   = tid >> 4;               // 16 j-groups of 8
    int p    = kk*ISL + isl;

    __shared__ float ash[Bn];
    __shared__ __align__(16) float csh[CH][Bn];
    __shared__ __align__(16) float Tsh[CH][TJ];

    for (int t = 0; t < Tn; t++) {
        // ---------- phase A: partial GEMM into g_part ----------
        if (tid < Bn) ash[tid] = g_alpha_a[((size_t)t*Bn + tid)*An + kk];

        float acc[4][8];
        #pragma unroll
        for (int a = 0; a < 4; a++)
            #pragma unroll
            for (int b = 0; b < 8; b++) acc[a][b] = 0.f;
        __syncthreads();

        for (int ic = 0; ic < ILEN; ic += CH) {
            int ib = i0 + ic;
            #pragma unroll
            for (int q = 0; q < (CH*Bn)/256; q++) {           // 8
                int e = tid + q*256; int il = e >> 6, n = e & 63;
                csh[il][n] = ash[n] * __ldcg(&g_belT[(size_t)(ib + il)*Bn + n]);
            }
            #pragma unroll
            for (int q = 0; q < (CH*TJ)/256; q++) {           // 16
                int e = tid + q*256; int il = e >> 7, jj = e & 127;
                Tsh[il][jj] = g_trans[((size_t)(kk*Sn + ib + il))*Sn + j0 + jj];
            }
            __syncthreads();
            for (int il = 0; il < CH; il++) {
                float4 cv = *reinterpret_cast<const float4*>(&csh[il][tn*4]);
                float4 t0 = *reinterpret_cast<const float4*>(&Tsh[il][tj*8]);
                float4 t1 = *reinterpret_cast<const float4*>(&Tsh[il][tj*8 + 4]);
                float cva[4] = {cv.x, cv.y, cv.z, cv.w};
                float tv[8]  = {t0.x, t0.y, t0.z, t0.w, t1.x, t1.y, t1.z, t1.w};
                #pragma unroll
                for (int a = 0; a < 4; a++)
                    #pragma unroll
                    for (int b = 0; b < 8; b++)
                        acc[a][b] = fmaf(cva[a], tv[b], acc[a][b]);
            }
            __syncthreads();
        }

        #pragma unroll
        for (int a = 0; a < 4; a++) {
            int n = tn*4 + a;
            float* op = &g_part[((size_t)p*Bn + n)*Sn + j0 + tj*8];
            __stcg(reinterpret_cast<float4*>(op),
                   make_float4(acc[a][0], acc[a][1], acc[a][2], acc[a][3]));
            __stcg(reinterpret_cast<float4*>(op + 4),
                   make_float4(acc[a][4], acc[a][5], acc[a][6], acc[a][7]));
        }

        grid_sync_dev();

        // ---------- phase B: reduce partials, log + obs, softmax -> b_post ----------
        if (unit < Bn) {
            int n = unit;
            float s0 = 0.f, s1 = 0.f;
            #pragma unroll 8
            for (int pp = 0; pp < NP; pp++) {
                const float* base = &g_part[((size_t)pp*Bn + n)*Sn + tid];
                s0 += __ldcg(base);
                s1 += __ldcg(base + 256);
            }
            const float* lo = &logp_o[((size_t)t*Bn + n)*Sn + tid];
            float v0 = logf(s0 + EPSF) + lo[0];
            float v1 = logf(s1 + EPSF) + lo[256];

            float* red = &csh[0][0];   // reuse smem (>= 512 floats)
            red[tid] = fmaxf(v0, v1); __syncthreads();
            for (int ss = 128; ss > 0; ss >>= 1) { if (tid < ss) red[tid] = fmaxf(red[tid], red[tid+ss]); __syncthreads(); }
            float m = red[0]; __syncthreads();
            float e0 = expf(v0 - m), e1 = expf(v1 - m);
            red[tid] = e0 + e1; __syncthreads();
            for (int ss = 128; ss > 0; ss >>= 1) { if (tid < ss) red[tid] += red[tid+ss]; __syncthreads(); }
            float inv = 1.f / red[0];
            float b0 = e0 * inv, b1 = e1 * inv;
            float* ob = &out_b[((size_t)t*Bn + n)*Sn + tid];
            ob[0]   = b0;
            ob[256] = b1;
            __stcg(&g_belT[(size_t)tid*Bn + n],       b0);
            __stcg(&g_belT[(size_t)(tid+256)*Bn + n], b1);
        }

        grid_sync_dev();
    }
}

// ---------------- post-scan plan: logits, softmax over A, tau-weighted sum over H ----------------
#define HB 4
__global__ void __launch_bounds__(256)
k_plan(const float* __restrict__ value,
       const float* __restrict__ alpha_b,
       float* __restrict__ out_pi) {
    int n  = blockIdx.x;
    int hq = blockIdx.y;          // 0..7, handles h = hq*HB .. +3
    int tid = threadIdx.x;        // 256
    int tk = tid & 15;            // k
    int tg = tid >> 4;            // t-group of 4

    __shared__ float Vsh[HB][32][17];
    __shared__ float Bsh[64][33];
    __shared__ float Lsh[HB][64][17];

    float acc[HB][4];
    #pragma unroll
    for (int h = 0; h < HB; h++)
        #pragma unroll
        for (int a = 0; a < 4; a++) acc[h][a] = 0.f;

    const float* bbase = alpha_b + (size_t)n*Sn;

    for (int i0 = 0; i0 < Sn; i0 += 32) {
        #pragma unroll
        for (int q = 0; q < 8; q++) {                  // HB*32*16 = 2048 elems
            int e = tid + q*256;
            int ii = e & 31, rest = e >> 5;
            int kk2 = rest & 15, hh = rest >> 4;
            Vsh[hh][ii][kk2] =
                value[(((size_t)(hq*HB + hh)*Bn + n)*An + kk2)*Sn + i0 + ii];
        }
        #pragma unroll
        for (int q = 0; q < 8; q++) {                  // 64*32 = 2048 elems
            int e = tid + q*256; int ii = e & 31, tt = e >> 5;
            Bsh[tt][ii] = bbase[(size_t)tt*Bn*Sn + i0 + ii];
        }
        __syncthreads();
        for (int ii = 0; ii < 32; ii++) {
            float bv[4];
            #pragma unroll
            for (int a = 0; a < 4; a++) bv[a] = Bsh[tg*4 + a][ii];
            #pragma unroll
            for (int h = 0; h < HB; h++) {
                float vv = Vsh[h][ii][tk];
                #pragma unroll
                for (int a = 0; a < 4; a++) acc[h][a] = fmaf(bv[a], vv, acc[h][a]);
            }
        }
        __syncthreads();
    }

    #pragma unroll
    for (int h = 0; h < HB; h++)
        #pragma unroll
        for (int a = 0; a < 4; a++) Lsh[h][tg*4 + a][tk] = acc[h][a];
    __syncthreads();

    // 256 threads = 4h x 64t; per-(h,t) softmax over 16 k + tau-weighted accumulate
    int hh = tid >> 6, t = tid & 63;
    float m = -1e30f;
    #pragma unroll
    for (int k = 0; k < An; k++) m = fmaxf(m, Lsh[hh][t][k]);
    float e[An]; float ssum = 0.f;
    #pragma unroll
    for (int k = 0; k < An; k++) { e[k] = expf(Lsh[hh][t][k] - m); ssum += e[k]; }
    float w = g_taupdf[hq*HB + hh] / ssum;
    #pragma unroll
    for (int k = 0; k < An; k++)
        atomicAdd(&out_pi[((size_t)t*Bn + n)*An + k], e[k] * w);
}

// ---------------- launch ----------------
extern "C" void kernel_launch(void* const* d_in, const int* in_sizes, int n_in,
                              void* d_out, int out_size) {
    const float* logp_o = (const float*)d_in[0];
    const float* logp_u = (const float*)d_in[1];
    const float* value  = (const float*)d_in[2];
    const float* b      = (const float*)d_in[3];
    const float* u      = (const float*)d_in[4];
    const float* v      = (const float*)d_in[5];
    const float* tau    = (const float*)d_in[6];

    float* out    = (float*)d_out;
    float* out_b  = out;                       // [T,B,S]
    float* out_pi = out + (size_t)Tn*Bn*Sn;    // [T,B,A]

    k_pv<<<An, 64>>>(u, v);
    k_gram<<<Sn, 128>>>(u);
    k_trans<<<dim3(Sn, An), 512>>>();
    k_taupdf<<<1, 32>>>(tau);
    k_alpha_a<<<(Tn*Bn + 127)/128, 128>>>(logp_u);
    k_init_bel<<<Bn, Sn>>>(b);

    k_scan<<<NUNITS, 256>>>(logp_o, out_b);

    cudaMemsetAsync(out_pi, 0, sizeof(float)*(size_t)Tn*Bn*An);
    k_plan<<<dim3(Bn, Hn/HB), 256>>>(value, out_b, out_pi);
}

// round 5
// speedup vs baseline: 2.2021x; 1.5131x over previous
#include <cuda_runtime.h>
#include <math.h>
#include <stdint.h>

#define Tn 64
#define Bn 64
#define Sn 512
#define An 16
#define Rn 64
#define Hn 32
#define EPSF 1e-6f

#define ISL 2            // i-slices per (j-tile, k)
#define NP  (An*ISL)     // 32 partial slabs
#define TJ 128
#define ILEN (Sn/ISL)    // 256
#define NUNITS 128       // persistent CTAs = 4 jt * 16 k * 2 isl

// ---------------- scratch (device globals; no allocation) ----------------
// T permuted into mma B-fragment layout: [k][i8][j8][lane][pair], tf32-rounded
__device__ __align__(16) float g_transP[(size_t)An*Sn*Sn];   // 16.8 MB
__device__ float g_G[Sn*Sn];                                  // 1 MB
__device__ float g_p[An*Sn];
__device__ float g_taupdf[Hn];
__device__ float g_alpha_a[(size_t)Tn*Bn*An];
__device__ __align__(16) float g_belT[Sn*Bn];                 // belief, transposed [i][n]
__device__ __align__(16) float g_part[(size_t)NP*Bn*Sn];      // 4 MB partials

__device__ int          g_bar_count;
__device__ volatile int g_bar_gen;

// ---------------- helpers ----------------
__device__ __forceinline__ uint32_t f2tf32(float x) {
    uint32_t u;
    asm("cvt.rna.tf32.f32 %0, %1;" : "=r"(u) : "f"(x));
    return u;
}

__device__ __forceinline__ void mma_tf32(float& c0, float& c1, float& c2, float& c3,
                                         uint32_t a0, uint32_t a1, uint32_t a2, uint32_t a3,
                                         uint32_t b0, uint32_t b1) {
    asm volatile("mma.sync.aligned.m16n8k8.row.col.f32.tf32.tf32.f32 "
                 "{%0,%1,%2,%3},{%4,%5,%6,%7},{%8,%9},{%0,%1,%2,%3};\n"
                 : "+f"(c0), "+f"(c1), "+f"(c2), "+f"(c3)
                 : "r"(a0), "r"(a1), "r"(a2), "r"(a3), "r"(b0), "r"(b1));
}

// ---------------- precompute: v_norm and p[k][i] = u[i].v_hat[k] ----------------
__global__ void k_pv(const float* __restrict__ u, const float* __restrict__ v) {
    int k = blockIdx.x;
    int t = threadIdx.x;  // 64 threads
    __shared__ float vn[Rn];
    __shared__ float sb[64];
    float x = v[k*Rn + t];
    sb[t] = x * x;
    __syncthreads();
    for (int s = 32; s > 0; s >>= 1) { if (t < s) sb[t] += sb[t+s]; __syncthreads(); }
    vn[t] = x * rsqrtf(sb[0]);
    __syncthreads();
    for (int i = t; i < Sn; i += 64) {
        float s = 0.f;
        #pragma unroll
        for (int r = 0; r < Rn; r++) s += u[i*Rn + r] * vn[r];
        g_p[k*Sn + i] = s;
    }
}

// ---------------- precompute: G[i][j] = u[i].u[j] ----------------
__global__ void k_gram(const float* __restrict__ u) {
    int i = blockIdx.x;
    int tid = threadIdx.x;  // 128
    __shared__ float ui[Rn];
    if (tid < Rn) ui[tid] = u[i*Rn + tid];
    __syncthreads();
    for (int j = tid; j < Sn; j += 128) {
        float s = 0.f;
        #pragma unroll
        for (int r = 0; r < Rn; r++) s += u[j*Rn + r] * ui[r];
        g_G[i*Sn + j] = s;
    }
}

// ---------------- precompute: transition rows (softmax over j), write permuted tf32 ----------------
__global__ void k_trans() {
    int i = blockIdx.x, k = blockIdx.y;
    int j = threadIdx.x;  // 512
    __shared__ float red[512];
    float pki = g_p[k*Sn + i];
    float w = g_G[i*Sn + j] - 2.f * pki * g_p[k*Sn + j];
    red[j] = w; __syncthreads();
    for (int s = 256; s > 0; s >>= 1) { if (j < s) red[j] = fmaxf(red[j], red[j+s]); __syncthreads(); }
    float m = red[0]; __syncthreads();
    float e = expf(w - m);
    red[j] = e; __syncthreads();
    for (int s = 256; s > 0; s >>= 1) { if (j < s) red[j] += red[j+s]; __syncthreads(); }
    float pr = e * (1.f / red[0]);
    // permuted B-fragment layout: [k][i8][j8][lane][pair]
    int lane = (i & 3) + 4 * (j & 7);
    int pair = (i >> 2) & 1;
    size_t idx = ((((size_t)(k*64 + (i >> 3))*64 + (j >> 3))*32 + lane) << 1) + pair;
    g_transP[idx] = __uint_as_float(f2tf32(pr));
}

// ---------------- precompute: normalized Poisson pdf over horizon ----------------
__global__ void k_taupdf(const float* __restrict__ tau) {
    int t = threadIdx.x;  // 32
    float rate = log1pf(expf(tau[0]));   // softplus
    float kk = (float)(t + 1);
    float lp = kk * logf(rate) - rate - lgammaf(kk + 1.f);
    float p = expf(lp);
    float s = p;
    #pragma unroll
    for (int o = 16; o > 0; o >>= 1) s += __shfl_xor_sync(0xffffffffu, s, o);
    g_taupdf[t] = p / s;
}

// ---------------- precompute: alpha_a = softmax(logp_u) over A ----------------
__global__ void k_alpha_a(const float* __restrict__ logp_u) {
    int idx = blockIdx.x * blockDim.x + threadIdx.x;
    if (idx >= Tn*Bn) return;
    const float* r = logp_u + (size_t)idx*An;
    float m = -1e30f;
    #pragma unroll
    for (int k = 0; k < An; k++) m = fmaxf(m, r[k]);
    float e[An]; float s = 0.f;
    #pragma unroll
    for (int k = 0; k < An; k++) { e[k] = expf(r[k] - m); s += e[k]; }
    float inv = 1.f / s;
    #pragma unroll
    for (int k = 0; k < An; k++) g_alpha_a[(size_t)idx*An + k] = e[k] * inv;
}

// ---------------- init belief (transposed) ----------------
__global__ void k_init_bel(const float* __restrict__ b) {
    int n = blockIdx.x, j = threadIdx.x;  // (Bn, Sn)
    g_belT[j*Bn + n] = b[n*Sn + j];
}

// ---------------- grid-wide barrier (all NUNITS CTAs co-resident) ----------------
__device__ __forceinline__ void grid_sync_dev() {
    __syncthreads();
    if (threadIdx.x == 0) {
        int old = g_bar_gen;
        __threadfence();
        int t = atomicAdd(&g_bar_count, 1);
        if (t == NUNITS - 1) {
            g_bar_count = 0;
            __threadfence();
            g_bar_gen = old + 1;
        } else {
            while (g_bar_gen == old) __nanosleep(64);
        }
    }
    __syncthreads();
    __threadfence();
}

// ---------------- fused persistent scan: 64 steps of tf32-MMA GEMM + post ----------------
__global__ void __launch_bounds__(256, 2)
k_scan(const float* __restrict__ logp_o, float* __restrict__ out_b) {
    int tid  = threadIdx.x;            // 256
    int unit = blockIdx.x;             // 0..127
    int jt   = unit & 3;
    int kk   = (unit >> 2) & 15;
    int isl  = unit >> 6;              // 0..1
    int j0   = jt * TJ;
    int i0   = isl * ILEN;             // 0 or 256
    int lane = tid & 31;
    int warp = tid >> 5;
    int gid  = lane >> 2;              // 0..7
    int tig  = lane & 3;               // 0..3
    int mw   = warp & 1;               // 2 warps over M (n)
    int nw   = warp >> 1;              // 4 warps over N (j)
    int nwb  = mw * 32;                // warp n base within 64
    int p    = kk*ISL + isl;

    __shared__ float ash[Bn];
    __shared__ __align__(16) uint32_t csh[32][72];   // c[n,i] tf32, stride 72 (bank-safe)
    __shared__ __align__(16) float2 Psh[4*16*32];    // B frags: [q][j8][lane], 16 KB
    __shared__ float red[512];

    for (int t = 0; t < Tn; t++) {
        // ---------- phase A: tensor-core partial GEMM into g_part ----------
        if (tid < Bn) ash[tid] = g_alpha_a[((size_t)t*Bn + tid)*An + kk];

        float c[2][4][4];
        #pragma unroll
        for (int mt = 0; mt < 2; mt++)
            #pragma unroll
            for (int nt = 0; nt < 4; nt++)
                #pragma unroll
                for (int r = 0; r < 4; r++) c[mt][nt][r] = 0.f;
        __syncthreads();

        #pragma unroll 1
        for (int chunk = 0; chunk < ILEN/32; chunk++) {    // 8 chunks of 32 i
            int ib = i0 + chunk*32;
            // stage A: csh[il][n] = tf32( a[n,k] * bel[ib+il, n] )
            #pragma unroll
            for (int q = 0; q < 8; q++) {
                int e = tid + q*256; int il = e >> 6, n = e & 63;
                float val = ash[n] * __ldcg(&g_belT[(size_t)(ib + il)*Bn + n]);
                csh[il][n] = f2tf32(val);
            }
            // stage B: contiguous copy of permuted T frags (4 i8-blocks x 1024 floats)
            {
                const float4* src = reinterpret_cast<const float4*>(g_transP);
                float4* dst = reinterpret_cast<float4*>(Psh);
                int i8b = ib >> 3;
                #pragma unroll
                for (int r = 0; r < 4; r++) {
                    int f = tid + r*256;
                    int q = f >> 8, rem = f & 255;
                    dst[f] = src[(size_t)(kk*64 + i8b + q)*1024 + jt*256 + rem];
                }
            }
            __syncthreads();
            #pragma unroll
            for (int q = 0; q < 4; q++) {                  // 4 mma k-steps of 8
                uint32_t a[2][4];
                #pragma unroll
                for (int mt = 0; mt < 2; mt++) {
                    int n0 = nwb + mt*16;
                    a[mt][0] = csh[q*8 + tig    ][n0 + gid    ];
                    a[mt][1] = csh[q*8 + tig    ][n0 + gid + 8];
                    a[mt][2] = csh[q*8 + tig + 4][n0 + gid    ];
                    a[mt][3] = csh[q*8 + tig + 4][n0 + gid + 8];
                }
                #pragma unroll
                for (int nt = 0; nt < 4; nt++) {
                    float2 bf = Psh[(q*16 + nw*4 + nt)*32 + lane];
                    uint32_t b0 = __float_as_uint(bf.x);
                    uint32_t b1 = __float_as_uint(bf.y);
                    #pragma unroll
                    for (int mt = 0; mt < 2; mt++)
                        mma_tf32(c[mt][nt][0], c[mt][nt][1], c[mt][nt][2], c[mt][nt][3],
                                 a[mt][0], a[mt][1], a[mt][2], a[mt][3], b0, b1);
                }
            }
            __syncthreads();
        }

        // write partial slab
        #pragma unroll
        for (int mt = 0; mt < 2; mt++) {
            int n_lo = nwb + mt*16 + gid;
            #pragma unroll
            for (int nt = 0; nt < 4; nt++) {
                int jcol = j0 + nw*32 + nt*8 + 2*tig;
                float* op0 = &g_part[((size_t)p*Bn + n_lo)*Sn + jcol];
                float* op1 = &g_part[((size_t)p*Bn + n_lo + 8)*Sn + jcol];
                __stcg(reinterpret_cast<float2*>(op0), make_float2(c[mt][nt][0], c[mt][nt][1]));
                __stcg(reinterpret_cast<float2*>(op1), make_float2(c[mt][nt][2], c[mt][nt][3]));
            }
        }

        grid_sync_dev();

        // ---------- phase B: reduce partials, log + obs, softmax -> b_post ----------
        if (unit < Bn) {
            int n = unit;
            float s0 = 0.f, s1 = 0.f;
            #pragma unroll 8
            for (int pp = 0; pp < NP; pp++) {
                const float* base = &g_part[((size_t)pp*Bn + n)*Sn + tid];
                s0 += __ldcg(base);
                s1 += __ldcg(base + 256);
            }
            const float* lo = &logp_o[((size_t)t*Bn + n)*Sn + tid];
            float v0 = logf(s0 + EPSF) + lo[0];
            float v1 = logf(s1 + EPSF) + lo[256];

            red[tid] = fmaxf(v0, v1); __syncthreads();
            for (int ss = 128; ss > 0; ss >>= 1) { if (tid < ss) red[tid] = fmaxf(red[tid], red[tid+ss]); __syncthreads(); }
            float m = red[0]; __syncthreads();
            float e0 = expf(v0 - m), e1 = expf(v1 - m);
            red[tid] = e0 + e1; __syncthreads();
            for (int ss = 128; ss > 0; ss >>= 1) { if (tid < ss) red[tid] += red[tid+ss]; __syncthreads(); }
            float inv = 1.f / red[0];
            float b0 = e0 * inv, b1 = e1 * inv;
            float* ob = &out_b[((size_t)t*Bn + n)*Sn + tid];
            ob[0]   = b0;
            ob[256] = b1;
            __stcg(&g_belT[(size_t)tid*Bn + n],       b0);
            __stcg(&g_belT[(size_t)(tid+256)*Bn + n], b1);
        }

        grid_sync_dev();
    }
}

// ---------------- post-scan plan: logits, softmax over A, tau-weighted sum over H ----------------
#define HB 4
__global__ void __launch_bounds__(256)
k_plan(const float* __restrict__ value,
       const float* __restrict__ alpha_b,
       float* __restrict__ out_pi) {
    int n  = blockIdx.x;
    int hq = blockIdx.y;          // 0..7, handles h = hq*HB .. +3
    int tid = threadIdx.x;        // 256
    int tk = tid & 15;            // k
    int tg = tid >> 4;            // t-group of 4

    __shared__ float Vsh[HB][32][17];
    __shared__ float Bsh[64][33];
    __shared__ float Lsh[HB][64][17];

    float acc[HB][4];
    #pragma unroll
    for (int h = 0; h < HB; h++)
        #pragma unroll
        for (int a = 0; a < 4; a++) acc[h][a] = 0.f;

    const float* bbase = alpha_b + (size_t)n*Sn;

    for (int i0 = 0; i0 < Sn; i0 += 32) {
        #pragma unroll
        for (int q = 0; q < 8; q++) {                  // HB*32*16 = 2048 elems
            int e = tid + q*256;
            int ii = e & 31, rest = e >> 5;
            int kk2 = rest & 15, hh = rest >> 4;
            Vsh[hh][ii][kk2] =
                value[(((size_t)(hq*HB + hh)*Bn + n)*An + kk2)*Sn + i0 + ii];
        }
        #pragma unroll
        for (int q = 0; q < 8; q++) {                  // 64*32 = 2048 elems
            int e = tid + q*256; int ii = e & 31, tt = e >> 5;
            Bsh[tt][ii] = bbase[(size_t)tt*Bn*Sn + i0 + ii];
        }
        __syncthreads();
        for (int ii = 0; ii < 32; ii++) {
            float bv[4];
            #pragma unroll
            for (int a = 0; a < 4; a++) bv[a] = Bsh[tg*4 + a][ii];
            #pragma unroll
            for (int h = 0; h < HB; h++) {
                float vv = Vsh[h][ii][tk];
                #pragma unroll
                for (int a = 0; a < 4; a++) acc[h][a] = fmaf(bv[a], vv, acc[h][a]);
            }
        }
        __syncthreads();
    }

    #pragma unroll
    for (int h = 0; h < HB; h++)
        #pragma unroll
        for (int a = 0; a < 4; a++) Lsh[h][tg*4 + a][tk] = acc[h][a];
    __syncthreads();

    int hh = tid >> 6, t = tid & 63;
    float m = -1e30f;
    #pragma unroll
    for (int k = 0; k < An; k++) m = fmaxf(m, Lsh[hh][t][k]);
    float e[An]; float ssum = 0.f;
    #pragma unroll
    for (int k = 0; k < An; k++) { e[k] = expf(Lsh[hh][t][k] - m); ssum += e[k]; }
    float w = g_taupdf[hq*HB + hh] / ssum;
    #pragma unroll
    for (int k = 0; k < An; k++)
        atomicAdd(&out_pi[((size_t)t*Bn + n)*An + k], e[k] * w);
}

// ---------------- launch ----------------
extern "C" void kernel_launch(void* const* d_in, const int* in_sizes, int n_in,
                              void* d_out, int out_size) {
    const float* logp_o = (const float*)d_in[0];
    const float* logp_u = (const float*)d_in[1];
    const float* value  = (const float*)d_in[2];
    const float* b      = (const float*)d_in[3];
    const float* u      = (const float*)d_in[4];
    const float* v      = (const float*)d_in[5];
    const float* tau    = (const float*)d_in[6];

    float* out    = (float*)d_out;
    float* out_b  = out;                       // [T,B,S]
    float* out_pi = out + (size_t)Tn*Bn*Sn;    // [T,B,A]

    k_pv<<<An, 64>>>(u, v);
    k_gram<<<Sn, 128>>>(u);
    k_trans<<<dim3(Sn, An), 512>>>();
    k_taupdf<<<1, 32>>>(tau);
    k_alpha_a<<<(Tn*Bn + 127)/128, 128>>>(logp_u);
    k_init_bel<<<Bn, Sn>>>(b);

    k_scan<<<NUNITS, 256>>>(logp_o, out_b);

    cudaMemsetAsync(out_pi, 0, sizeof(float)*(size_t)Tn*Bn*An);
    k_plan<<<dim3(Bn, Hn/HB), 256>>>(value, out_b, out_pi);
}

// round 6
// speedup vs baseline: 2.4571x; 1.1158x over previous
#include <cuda_runtime.h>
#include <math.h>
#include <stdint.h>

#define Tn 64
#define Bn 64
#define Sn 512
#define An 16
#define Rn 64
#define Hn 32
#define EPSF 1e-6f

#define ISL 2            // i-slices per (j-tile, k)
#define NP  (An*ISL)     // 32 partial slabs
#define TJ 128
#define ILEN (Sn/ISL)    // 256
#define NUNITS 128       // persistent CTAs = 4 jt * 16 k * 2 isl

// dynamic smem partition (floats)
#define TSL_F   32768            // T slab: 256 i x 128 j as [i8][j8][lane][pair]
#define CSH_STRIDE 72
#define CSH_F   (256*CSH_STRIDE) // 18432
#define SMEM_F  (TSL_F + CSH_F + 64 + 512)

// ---------------- scratch (device globals; no allocation) ----------------
// T permuted into mma B-fragment layout: [k][i8][j8][lane][pair], tf32-rounded
__device__ __align__(16) float g_transP[(size_t)An*Sn*Sn];   // 16.8 MB
__device__ float g_G[Sn*Sn];                                  // 1 MB
__device__ float g_p[An*Sn];
__device__ float g_taupdf[Hn];
__device__ float g_alpha_a[(size_t)Tn*Bn*An];
__device__ __align__(16) float g_belT[Sn*Bn];                 // belief, transposed [i][n]
__device__ __align__(16) float g_part[(size_t)NP*Bn*Sn];      // 4 MB partials

__device__ int          g_bar_count;
__device__ volatile int g_bar_gen;

// ---------------- helpers ----------------
__device__ __forceinline__ uint32_t f2tf32(float x) {
    uint32_t u;
    asm("cvt.rna.tf32.f32 %0, %1;" : "=r"(u) : "f"(x));
    return u;
}

__device__ __forceinline__ void mma_tf32(float& c0, float& c1, float& c2, float& c3,
                                         uint32_t a0, uint32_t a1, uint32_t a2, uint32_t a3,
                                         uint32_t b0, uint32_t b1) {
    asm volatile("mma.sync.aligned.m16n8k8.row.col.f32.tf32.tf32.f32 "
                 "{%0,%1,%2,%3},{%4,%5,%6,%7},{%8,%9},{%0,%1,%2,%3};\n"
                 : "+f"(c0), "+f"(c1), "+f"(c2), "+f"(c3)
                 : "r"(a0), "r"(a1), "r"(a2), "r"(a3), "r"(b0), "r"(b1));
}

// ---------------- precompute: v_norm and p[k][i] = u[i].v_hat[k] ----------------
__global__ void k_pv(const float* __restrict__ u, const float* __restrict__ v) {
    int k = blockIdx.x;
    int t = threadIdx.x;  // 64 threads
    __shared__ float vn[Rn];
    __shared__ float sb[64];
    float x = v[k*Rn + t];
    sb[t] = x * x;
    __syncthreads();
    for (int s = 32; s > 0; s >>= 1) { if (t < s) sb[t] += sb[t+s]; __syncthreads(); }
    vn[t] = x * rsqrtf(sb[0]);
    __syncthreads();
    for (int i = t; i < Sn; i += 64) {
        float s = 0.f;
        #pragma unroll
        for (int r = 0; r < Rn; r++) s += u[i*Rn + r] * vn[r];
        g_p[k*Sn + i] = s;
    }
}

// ---------------- precompute: G[i][j] = u[i].u[j] ----------------
__global__ void k_gram(const float* __restrict__ u) {
    int i = blockIdx.x;
    int tid = threadIdx.x;  // 128
    __shared__ float ui[Rn];
    if (tid < Rn) ui[tid] = u[i*Rn + tid];
    __syncthreads();
    for (int j = tid; j < Sn; j += 128) {
        float s = 0.f;
        #pragma unroll
        for (int r = 0; r < Rn; r++) s += u[j*Rn + r] * ui[r];
        g_G[i*Sn + j] = s;
    }
}

// ---------------- precompute: transition softmax + permuted tf32, coalesced writes ----------------
// one block per (i8, k): 8 row-softmaxes, then a contiguous 16 KB fragment-block store
__global__ void k_trans8() {
    int i8 = blockIdx.x, k = blockIdx.y;
    int j = threadIdx.x;  // 512
    __shared__ float red[512];
    __shared__ float stage[4096];
    float pkj = g_p[k*Sn + j];

    #pragma unroll 1
    for (int r = 0; r < 8; r++) {
        int i = i8*8 + r;
        float w = g_G[i*Sn + j] - 2.f * g_p[k*Sn + i] * pkj;
        red[j] = w; __syncthreads();
        for (int s = 256; s > 0; s >>= 1) { if (j < s) red[j] = fmaxf(red[j], red[j+s]); __syncthreads(); }
        float m = red[0]; __syncthreads();
        float e = expf(w - m);
        red[j] = e; __syncthreads();
        for (int s = 256; s > 0; s >>= 1) { if (j < s) red[j] += red[j+s]; __syncthreads(); }
        float pr = e * (1.f / red[0]);
        // fragment position within this i8 block: [j8][lane][pair]
        stage[(j >> 3)*64 + ((r & 3) + 4*(j & 7))*2 + (r >> 2)] = __uint_as_float(f2tf32(pr));
        __syncthreads();
    }

    const float4* s4 = reinterpret_cast<const float4*>(stage);
    float4* d4 = reinterpret_cast<float4*>(g_transP + (size_t)(k*64 + i8)*4096);
    d4[j]       = s4[j];
    d4[j + 512] = s4[j + 512];
}

// ---------------- precompute: normalized Poisson pdf over horizon ----------------
__global__ void k_taupdf(const float* __restrict__ tau) {
    int t = threadIdx.x;  // 32
    float rate = log1pf(expf(tau[0]));   // softplus
    float kk = (float)(t + 1);
    float lp = kk * logf(rate) - rate - lgammaf(kk + 1.f);
    float p = expf(lp);
    float s = p;
    #pragma unroll
    for (int o = 16; o > 0; o >>= 1) s += __shfl_xor_sync(0xffffffffu, s, o);
    g_taupdf[t] = p / s;
}

// ---------------- precompute: alpha_a = softmax(logp_u) over A ----------------
__global__ void k_alpha_a(const float* __restrict__ logp_u) {
    int idx = blockIdx.x * blockDim.x + threadIdx.x;
    if (idx >= Tn*Bn) return;
    const float* r = logp_u + (size_t)idx*An;
    float m = -1e30f;
    #pragma unroll
    for (int k = 0; k < An; k++) m = fmaxf(m, r[k]);
    float e[An]; float s = 0.f;
    #pragma unroll
    for (int k = 0; k < An; k++) { e[k] = expf(r[k] - m); s += e[k]; }
    float inv = 1.f / s;
    #pragma unroll
    for (int k = 0; k < An; k++) g_alpha_a[(size_t)idx*An + k] = e[k] * inv;
}

// ---------------- init belief (transposed) ----------------
__global__ void k_init_bel(const float* __restrict__ b) {
    int n = blockIdx.x, j = threadIdx.x;  // (Bn, Sn)
    g_belT[j*Bn + n] = b[n*Sn + j];
}

// ---------------- grid-wide barrier (all NUNITS CTAs co-resident) ----------------
__device__ __forceinline__ void grid_sync_dev() {
    __syncthreads();
    if (threadIdx.x == 0) {
        int old = g_bar_gen;
        __threadfence();
        int t = atomicAdd(&g_bar_count, 1);
        if (t == NUNITS - 1) {
            g_bar_count = 0;
            __threadfence();
            g_bar_gen = old + 1;
        } else {
            while (g_bar_gen == old) __nanosleep(64);
        }
    }
    __syncthreads();
    __threadfence();
}

// ---------------- fused persistent scan: SMEM-resident T, 64 steps ----------------
__global__ void __launch_bounds__(256, 1)
k_scan(const float* __restrict__ logp_o, float* __restrict__ out_b) {
    extern __shared__ float smem[];
    float*    Tsl = smem;                       // 32768 f: [i8l][j8l][lane][pair]
    uint32_t* csh = (uint32_t*)(smem + TSL_F);  // [256][72]
    float*    ash = smem + TSL_F + CSH_F;       // 64
    float*    red = ash + 64;                   // 512

    int tid  = threadIdx.x;            // 256
    int unit = blockIdx.x;             // 0..127
    int jt   = unit & 3;
    int kk   = (unit >> 2) & 15;
    int isl  = unit >> 6;              // 0..1
    int j0   = jt * TJ;
    int i0   = isl * ILEN;             // 0 or 256
    int lane = tid & 31;
    int warp = tid >> 5;
    int gid  = lane >> 2;              // 0..7
    int tig  = lane & 3;               // 0..3
    int mw   = warp & 1;               // 2 warps over M (n)
    int nw   = warp >> 1;              // 4 warps over N (j)
    int nwb  = mw * 32;                // warp n base within 64
    int p    = kk*ISL + isl;

    // ---- one-time: load this CTA's permuted T slab into SMEM (128 KB) ----
    {
        const float4* src = reinterpret_cast<const float4*>(g_transP);
        float4* dst = reinterpret_cast<float4*>(Tsl);
        #pragma unroll
        for (int q = 0; q < 32; q++) {             // 8192 float4 / 256 thr
            int f = tid + q*256;
            int blk = f >> 4, r = f & 15;          // blk = i8l*16 + j8l
            int i8l = blk >> 4, j8l = blk & 15;
            dst[f] = src[(size_t)((kk*64 + isl*32 + i8l)*64 + jt*16 + j8l)*16 + r];
        }
    }
    const float2* Tsl2 = reinterpret_cast<const float2*>(Tsl);
    __syncthreads();

    int nst = tid & 63;                // staging n (constant per thread)
    int il0 = tid >> 6;                // staging i base (stride 4)

    for (int t = 0; t < Tn; t++) {
        // ---------- phase A: stage full coefficient tile, then pure MMA ----------
        if (tid < Bn) ash[tid] = g_alpha_a[((size_t)t*Bn + tid)*An + kk];
        __syncthreads();
        float an = ash[nst];
        #pragma unroll 8
        for (int q = 0; q < 64; q++) {
            int il = il0 + q*4;
            float val = an * __ldcg(&g_belT[(size_t)(i0 + il)*Bn + nst]);
            csh[il*CSH_STRIDE + nst] = f2tf32(val);
        }
        __syncthreads();

        float c[2][4][4];
        #pragma unroll
        for (int mt = 0; mt < 2; mt++)
            #pragma unroll
            for (int nt = 0; nt < 4; nt++)
                #pragma unroll
                for (int r = 0; r < 4; r++) c[mt][nt][r] = 0.f;

        #pragma unroll 4
        for (int ks = 0; ks < 32; ks++) {          // 32 k-steps of 8 i
            int r0 = ks*8;
            uint32_t a[2][4];
            #pragma unroll
            for (int mt = 0; mt < 2; mt++) {
                int n0 = nwb + mt*16;
                a[mt][0] = csh[(r0 + tig    )*CSH_STRIDE + n0 + gid    ];
                a[mt][1] = csh[(r0 + tig    )*CSH_STRIDE + n0 + gid + 8];
                a[mt][2] = csh[(r0 + tig + 4)*CSH_STRIDE + n0 + gid    ];
                a[mt][3] = csh[(r0 + tig + 4)*CSH_STRIDE + n0 + gid + 8];
            }
            #pragma unroll
            for (int nt = 0; nt < 4; nt++) {
                float2 bf = Tsl2[(ks*16 + nw*4 + nt)*32 + lane];
                uint32_t b0 = __float_as_uint(bf.x);
                uint32_t b1 = __float_as_uint(bf.y);
                #pragma unroll
                for (int mt = 0; mt < 2; mt++)
                    mma_tf32(c[mt][nt][0], c[mt][nt][1], c[mt][nt][2], c[mt][nt][3],
                             a[mt][0], a[mt][1], a[mt][2], a[mt][3], b0, b1);
            }
        }

        // write partial slab
        #pragma unroll
        for (int mt = 0; mt < 2; mt++) {
            int n_lo = nwb + mt*16 + gid;
            #pragma unroll
            for (int nt = 0; nt < 4; nt++) {
                int jcol = j0 + nw*32 + nt*8 + 2*tig;
                float* op0 = &g_part[((size_t)p*Bn + n_lo)*Sn + jcol];
                float* op1 = &g_part[((size_t)p*Bn + n_lo + 8)*Sn + jcol];
                __stcg(reinterpret_cast<float2*>(op0), make_float2(c[mt][nt][0], c[mt][nt][1]));
                __stcg(reinterpret_cast<float2*>(op1), make_float2(c[mt][nt][2], c[mt][nt][3]));
            }
        }

        grid_sync_dev();

        // ---------- phase B: reduce partials, log + obs, softmax -> b_post ----------
        if (unit < Bn) {
            int n = unit;
            float s0 = 0.f, s1 = 0.f;
            #pragma unroll 8
            for (int pp = 0; pp < NP; pp++) {
                const float* base = &g_part[((size_t)pp*Bn + n)*Sn + tid];
                s0 += __ldcg(base);
                s1 += __ldcg(base + 256);
            }
            const float* lo = &logp_o[((size_t)t*Bn + n)*Sn + tid];
            float v0 = logf(s0 + EPSF) + lo[0];
            float v1 = logf(s1 + EPSF) + lo[256];

            red[tid] = fmaxf(v0, v1); __syncthreads();
            for (int ss = 128; ss > 0; ss >>= 1) { if (tid < ss) red[tid] = fmaxf(red[tid], red[tid+ss]); __syncthreads(); }
            float m = red[0]; __syncthreads();
            float e0 = expf(v0 - m), e1 = expf(v1 - m);
            red[tid] = e0 + e1; __syncthreads();
            for (int ss = 128; ss > 0; ss >>= 1) { if (tid < ss) red[tid] += red[tid+ss]; __syncthreads(); }
            float inv = 1.f / red[0];
            float b0 = e0 * inv, b1 = e1 * inv;
            float* ob = &out_b[((size_t)t*Bn + n)*Sn + tid];
            ob[0]   = b0;
            ob[256] = b1;
            __stcg(&g_belT[(size_t)tid*Bn + n],       b0);
            __stcg(&g_belT[(size_t)(tid+256)*Bn + n], b1);
        }

        grid_sync_dev();
    }
}

// ---------------- post-scan plan: logits, softmax over A, tau-weighted sum over H ----------------
#define HB 4
__global__ void __launch_bounds__(256)
k_plan(const float* __restrict__ value,
       const float* __restrict__ alpha_b,
       float* __restrict__ out_pi) {
    int n  = blockIdx.x;
    int hq = blockIdx.y;          // 0..7, handles h = hq*HB .. +3
    int tid = threadIdx.x;        // 256
    int tk = tid & 15;            // k
    int tg = tid >> 4;            // t-group of 4

    __shared__ float Vsh[HB][32][17];
    __shared__ float Bsh[64][33];
    __shared__ float Lsh[HB][64][17];

    float acc[HB][4];
    #pragma unroll
    for (int h = 0; h < HB; h++)
        #pragma unroll
        for (int a = 0; a < 4; a++) acc[h][a] = 0.f;

    const float* bbase = alpha_b + (size_t)n*Sn;

    for (int i0 = 0; i0 < Sn; i0 += 32) {
        #pragma unroll
        for (int q = 0; q < 8; q++) {                  // HB*32*16 = 2048 elems
            int e = tid + q*256;
            int ii = e & 31, rest = e >> 5;
            int kk2 = rest & 15, hh = rest >> 4;
            Vsh[hh][ii][kk2] =
                value[(((size_t)(hq*HB + hh)*Bn + n)*An + kk2)*Sn + i0 + ii];
        }
        #pragma unroll
        for (int q = 0; q < 8; q++) {                  // 64*32 = 2048 elems
            int e = tid + q*256; int ii = e & 31, tt = e >> 5;
            Bsh[tt][ii] = bbase[(size_t)tt*Bn*Sn + i0 + ii];
        }
        __syncthreads();
        for (int ii = 0; ii < 32; ii++) {
            float bv[4];
            #pragma unroll
            for (int a = 0; a < 4; a++) bv[a] = Bsh[tg*4 + a][ii];
            #pragma unroll
            for (int h = 0; h < HB; h++) {
                float vv = Vsh[h][ii][tk];
                #pragma unroll
                for (int a = 0; a < 4; a++) acc[h][a] = fmaf(bv[a], vv, acc[h][a]);
            }
        }
        __syncthreads();
    }

    #pragma unroll
    for (int h = 0; h < HB; h++)
        #pragma unroll
        for (int a = 0; a < 4; a++) Lsh[h][tg*4 + a][tk] = acc[h][a];
    __syncthreads();

    int hh = tid >> 6, t = tid & 63;
    float m = -1e30f;
    #pragma unroll
    for (int k = 0; k < An; k++) m = fmaxf(m, Lsh[hh][t][k]);
    float e[An]; float ssum = 0.f;
    #pragma unroll
    for (int k = 0; k < An; k++) { e[k] = expf(Lsh[hh][t][k] - m); ssum += e[k]; }
    float w = g_taupdf[hq*HB + hh] / ssum;
    #pragma unroll
    for (int k = 0; k < An; k++)
        atomicAdd(&out_pi[((size_t)t*Bn + n)*An + k], e[k] * w);
}

// ---------------- launch ----------------
extern "C" void kernel_launch(void* const* d_in, const int* in_sizes, int n_in,
                              void* d_out, int out_size) {
    const float* logp_o = (const float*)d_in[0];
    const float* logp_u = (const float*)d_in[1];
    const float* value  = (const float*)d_in[2];
    const float* b      = (const float*)d_in[3];
    const float* u      = (const float*)d_in[4];
    const float* v      = (const float*)d_in[5];
    const float* tau    = (const float*)d_in[6];

    float* out    = (float*)d_out;
    float* out_b  = out;                       // [T,B,S]
    float* out_pi = out + (size_t)Tn*Bn*Sn;    // [T,B,A]

    static int smem_set = 0;
    if (!smem_set) {
        cudaFuncSetAttribute(k_scan, cudaFuncAttributeMaxDynamicSharedMemorySize,
                             SMEM_F * (int)sizeof(float));
        smem_set = 1;
    }

    k_pv<<<An, 64>>>(u, v);
    k_gram<<<Sn, 128>>>(u);
    k_trans8<<<dim3(Sn/8, An), 512>>>();
    k_taupdf<<<1, 32>>>(tau);
    k_alpha_a<<<(Tn*Bn + 127)/128, 128>>>(logp_u);
    k_init_bel<<<Bn, Sn>>>(b);

    k_scan<<<NUNITS, 256, SMEM_F * (int)sizeof(float)>>>(logp_o, out_b);

    cudaMemsetAsync(out_pi, 0, sizeof(float)*(size_t)Tn*Bn*An);
    k_plan<<<dim3(Bn, Hn/HB), 256>>>(value, out_b, out_pi);
}

// round 9
// speedup vs baseline: 3.0580x; 1.2446x over previous
#include <cuda_runtime.h>
#include <math.h>
#include <stdint.h>

#define Tn 64
#define Bn 64
#define Sn 512
#define An 16
#define Rn 64
#define Hn 32
#define EPSF 1e-6f

#define ISL 2            // i-slices per (j-tile, k)
#define NP  (An*ISL)     // 32 partial slabs
#define TJ 128
#define ILEN (Sn/ISL)    // 256
#define NUNITS 128       // persistent CTAs = 4 jt * 16 k * 2 isl

// dynamic smem partition (floats)
#define TSL_F   32768            // T slab: 256 i x 128 j as [i8][j8][lane][pair]
#define CSH_STRIDE 72
#define CSH_F   (256*CSH_STRIDE) // 18432
#define SMEM_F  (TSL_F + CSH_F + 64 + 64)

// ---------------- scratch (device globals; no allocation) ----------------
// T permuted into mma B-fragment layout: [k][i8][j8][lane][pair], tf32-rounded
__device__ __align__(16) float g_transP[(size_t)An*Sn*Sn];   // 16.8 MB
__device__ float g_G[Sn*Sn];                                  // 1 MB
__device__ float g_p[An*Sn];
__device__ float g_taupdf[Hn];
__device__ float g_alpha_a[(size_t)Tn*Bn*An];
__device__ __align__(16) float g_belT[Sn*Bn];                 // belief (unnormalized), [i][n]
__device__ __align__(16) float g_part[(size_t)NP*Bn*Sn];      // 4 MB partials
__device__ __align__(16) float g_po[(size_t)Tn*Bn*Sn];        // exp(logp_o), 8 MB
__device__ float g_normAll[Tn*2*Bn];                          // per (t, jhalf, n) norm partials

__device__ int          g_bar_count;
__device__ volatile int g_bar_gen;

// ---------------- helpers ----------------
__device__ __forceinline__ uint32_t f2tf32(float x) {
    uint32_t u;
    asm("cvt.rna.tf32.f32 %0, %1;" : "=r"(u) : "f"(x));
    return u;
}

__device__ __forceinline__ void mma_tf32(float& c0, float& c1, float& c2, float& c3,
                                         uint32_t a0, uint32_t a1, uint32_t a2, uint32_t a3,
                                         uint32_t b0, uint32_t b1) {
    asm volatile("mma.sync.aligned.m16n8k8.row.col.f32.tf32.tf32.f32 "
                 "{%0,%1,%2,%3},{%4,%5,%6,%7},{%8,%9},{%0,%1,%2,%3};\n"
                 : "+f"(c0), "+f"(c1), "+f"(c2), "+f"(c3)
                 : "r"(a0), "r"(a1), "r"(a2), "r"(a3), "r"(b0), "r"(b1));
}

// ---------------- precompute: v_norm and p[k][i] = u[i].v_hat[k] ----------------
__global__ void k_pv(const float* __restrict__ u, const float* __restrict__ v) {
    int k = blockIdx.x;
    int t = threadIdx.x;  // 64 threads
    __shared__ float vn[Rn];
    __shared__ float sb[64];
    float x = v[k*Rn + t];
    sb[t] = x * x;
    __syncthreads();
    for (int s = 32; s > 0; s >>= 1) { if (t < s) sb[t] += sb[t+s]; __syncthreads(); }
    vn[t] = x * rsqrtf(sb[0]);
    __syncthreads();
    for (int i = t; i < Sn; i += 64) {
        float s = 0.f;
        #pragma unroll
        for (int r = 0; r < Rn; r++) s += u[i*Rn + r] * vn[r];
        g_p[k*Sn + i] = s;
    }
}

// ---------------- precompute: G[i][j] = u[i].u[j] ----------------
__global__ void k_gram(const float* __restrict__ u) {
    int i = blockIdx.x;
    int tid = threadIdx.x;  // 128
    __shared__ float ui[Rn];
    if (tid < Rn) ui[tid] = u[i*Rn + tid];
    __syncthreads();
    for (int j = tid; j < Sn; j += 128) {
        float s = 0.f;
        #pragma unroll
        for (int r = 0; r < Rn; r++) s += u[j*Rn + r] * ui[r];
        g_G[i*Sn + j] = s;
    }
}

// ---------------- precompute: transition softmax + permuted tf32, coalesced writes ----------------
__global__ void k_trans8() {
    int i8 = blockIdx.x, k = blockIdx.y;
    int j = threadIdx.x;  // 512
    __shared__ float red[512];
    __shared__ float stage[4096];
    float pkj = g_p[k*Sn + j];

    #pragma unroll 1
    for (int r = 0; r < 8; r++) {
        int i = i8*8 + r;
        float w = g_G[i*Sn + j] - 2.f * g_p[k*Sn + i] * pkj;
        red[j] = w; __syncthreads();
        for (int s = 256; s > 0; s >>= 1) { if (j < s) red[j] = fmaxf(red[j], red[j+s]); __syncthreads(); }
        float m = red[0]; __syncthreads();
        float e = expf(w - m);
        red[j] = e; __syncthreads();
        for (int s = 256; s > 0; s >>= 1) { if (j < s) red[j] += red[j+s]; __syncthreads(); }
        float pr = e * (1.f / red[0]);
        stage[(j >> 3)*64 + ((r & 3) + 4*(j & 7))*2 + (r >> 2)] = __uint_as_float(f2tf32(pr));
        __syncthreads();
    }

    const float4* s4 = reinterpret_cast<const float4*>(stage);
    float4* d4 = reinterpret_cast<float4*>(g_transP + (size_t)(k*64 + i8)*4096);
    d4[j]       = s4[j];
    d4[j + 512] = s4[j + 512];
}

// ---------------- precompute: normalized Poisson pdf over horizon ----------------
__global__ void k_taupdf(const float* __restrict__ tau) {
    int t = threadIdx.x;  // 32
    float rate = log1pf(expf(tau[0]));   // softplus
    float kk = (float)(t + 1);
    float lp = kk * logf(rate) - rate - lgammaf(kk + 1.f);
    float p = expf(lp);
    float s = p;
    #pragma unroll
    for (int o = 16; o > 0; o >>= 1) s += __shfl_xor_sync(0xffffffffu, s, o);
    g_taupdf[t] = p / s;
}

// ---------------- precompute: alpha_a = softmax(logp_u) over A ----------------
__global__ void k_alpha_a(const float* __restrict__ logp_u) {
    int idx = blockIdx.x * blockDim.x + threadIdx.x;
    if (idx >= Tn*Bn) return;
    const float* r = logp_u + (size_t)idx*An;
    float m = -1e30f;
    #pragma unroll
    for (int k = 0; k < An; k++) m = fmaxf(m, r[k]);
    float e[An]; float s = 0.f;
    #pragma unroll
    for (int k = 0; k < An; k++) { e[k] = expf(r[k] - m); s += e[k]; }
    float inv = 1.f / s;
    #pragma unroll
    for (int k = 0; k < An; k++) g_alpha_a[(size_t)idx*An + k] = e[k] * inv;
}

// ---------------- precompute: po = exp(logp_o) ----------------
__global__ void k_po(const float* __restrict__ logp_o) {
    size_t idx = (size_t)blockIdx.x * 512 + threadIdx.x;
    g_po[idx] = expf(logp_o[idx]);
}

// ---------------- init belief (transposed) ----------------
__global__ void k_init_bel(const float* __restrict__ b) {
    int n = blockIdx.x, j = threadIdx.x;  // (Bn, Sn)
    g_belT[j*Bn + n] = b[n*Sn + j];
}

// ---------------- grid-wide barrier (all NUNITS CTAs co-resident) ----------------
__device__ __forceinline__ void grid_sync_dev() {
    __syncthreads();
    if (threadIdx.x == 0) {
        int old = g_bar_gen;
        __threadfence();
        int t = atomicAdd(&g_bar_count, 1);
        if (t == NUNITS - 1) {
            g_bar_count = 0;
            __threadfence();
            g_bar_gen = old + 1;
        } else {
            while (g_bar_gen == old) __nanosleep(64);
        }
    }
    __syncthreads();
    __threadfence();
}

// ---------------- fused persistent scan: SMEM-resident T, 64 steps ----------------
__global__ void __launch_bounds__(256, 1)
k_scan(float* __restrict__ out_b) {
    extern __shared__ float smem[];
    float*    Tsl = smem;                       // 32768 f: [i8l][j8l][lane][pair]
    uint32_t* csh = (uint32_t*)(smem + TSL_F);  // [256][72]
    float*    ash = smem + TSL_F + CSH_F;       // 64
    float*    red = ash + 64;                   // 64 (warp partials)

    int tid  = threadIdx.x;            // 256
    int unit = blockIdx.x;             // 0..127
    int jt   = unit & 3;
    int kk   = (unit >> 2) & 15;
    int isl  = unit >> 6;              // 0..1
    int j0   = jt * TJ;
    int i0   = isl * ILEN;             // 0 or 256
    int lane = tid & 31;
    int warp = tid >> 5;
    int gid  = lane >> 2;              // 0..7
    int tig  = lane & 3;               // 0..3
    int mw   = warp & 1;               // 2 warps over M (n)
    int nw   = warp >> 1;              // 4 warps over N (j)
    int nwb  = mw * 32;                // warp n base within 64
    int p    = kk*ISL + isl;

    // phase-B identity (all 128 CTAs participate)
    int bn = unit >> 1;                // batch n
    int jh = unit & 1;                 // j half
    int bj = jh*256 + tid;             // j column

    // ---- one-time: load this CTA's permuted T slab into SMEM (128 KB) ----
    {
        const float4* src = reinterpret_cast<const float4*>(g_transP);
        float4* dst = reinterpret_cast<float4*>(Tsl);
        #pragma unroll
        for (int q = 0; q < 32; q++) {             // 8192 float4 / 256 thr
            int f = tid + q*256;
            int blk = f >> 4, r = f & 15;          // blk = i8l*16 + j8l
            int i8l = blk >> 4, j8l = blk & 15;
            dst[f] = src[(size_t)((kk*64 + isl*32 + i8l)*64 + jt*16 + j8l)*16 + r];
        }
    }
    const float2* Tsl2 = reinterpret_cast<const float2*>(Tsl);

    int n4  = (tid & 15) * 4;          // staging n base
    int ilb = tid >> 4;                // staging i base (stride 16)
    __syncthreads();

    for (int t = 0; t < Tn; t++) {
        // ---------- phase A: stage coefficient tile (inv-norm folded), pure MMA ----------
        if (tid < Bn) {
            float a = g_alpha_a[((size_t)t*Bn + tid)*An + kk];
            if (t > 0) {
                float q0 = __ldcg(&g_normAll[((t-1)*2 + 0)*Bn + tid]);
                float q1 = __ldcg(&g_normAll[((t-1)*2 + 1)*Bn + tid]);
                a *= 1.f / (q0 + q1);
            }
            ash[tid] = a;
        }
        __syncthreads();
        {
            float4 a4 = *reinterpret_cast<const float4*>(&ash[n4]);
            #pragma unroll
            for (int q = 0; q < 16; q++) {
                int il = ilb + q*16;
                float4 b4 = __ldcg(reinterpret_cast<const float4*>(
                                   &g_belT[(size_t)(i0 + il)*Bn + n4]));
                uint4 o;
                o.x = f2tf32(a4.x * b4.x);
                o.y = f2tf32(a4.y * b4.y);
                o.z = f2tf32(a4.z * b4.z);
                o.w = f2tf32(a4.w * b4.w);
                *reinterpret_cast<uint4*>(&csh[il*CSH_STRIDE + n4]) = o;
            }
        }
        __syncthreads();

        float c[2][4][4];
        #pragma unroll
        for (int mt = 0; mt < 2; mt++)
            #pragma unroll
            for (int nt = 0; nt < 4; nt++)
                #pragma unroll
                for (int r = 0; r < 4; r++) c[mt][nt][r] = 0.f;

        #pragma unroll 4
        for (int ks = 0; ks < 32; ks++) {          // 32 k-steps of 8 i
            int r0 = ks*8;
            uint32_t a[2][4];
            #pragma unroll
            for (int mt = 0; mt < 2; mt++) {
                int n0 = nwb + mt*16;
                a[mt][0] = csh[(r0 + tig    )*CSH_STRIDE + n0 + gid    ];
                a[mt][1] = csh[(r0 + tig    )*CSH_STRIDE + n0 + gid + 8];
                a[mt][2] = csh[(r0 + tig + 4)*CSH_STRIDE + n0 + gid    ];
                a[mt][3] = csh[(r0 + tig + 4)*CSH_STRIDE + n0 + gid + 8];
            }
            #pragma unroll
            for (int nt = 0; nt < 4; nt++) {
                float2 bf = Tsl2[(ks*16 + nw*4 + nt)*32 + lane];
                uint32_t b0 = __float_as_uint(bf.x);
                uint32_t b1 = __float_as_uint(bf.y);
                #pragma unroll
                for (int mt = 0; mt < 2; mt++)
                    mma_tf32(c[mt][nt][0], c[mt][nt][1], c[mt][nt][2], c[mt][nt][3],
                             a[mt][0], a[mt][1], a[mt][2], a[mt][3], b0, b1);
            }
        }

        // write partial slab
        #pragma unroll
        for (int mt = 0; mt < 2; mt++) {
            int n_lo = nwb + mt*16 + gid;
            #pragma unroll
            for (int nt = 0; nt < 4; nt++) {
                int jcol = j0 + nw*32 + nt*8 + 2*tig;
                float* op0 = &g_part[((size_t)p*Bn + n_lo)*Sn + jcol];
                float* op1 = &g_part[((size_t)p*Bn + n_lo + 8)*Sn + jcol];
                __stcg(reinterpret_cast<float2*>(op0), make_float2(c[mt][nt][0], c[mt][nt][1]));
                __stcg(reinterpret_cast<float2*>(op1), make_float2(c[mt][nt][2], c[mt][nt][3]));
            }
        }

        grid_sync_dev();

        // ---------- phase B: reduce partials, (s+eps)*po, deferred-norm belief ----------
        {
            float s = 0.f;
            #pragma unroll 8
            for (int pp = 0; pp < NP; pp++)
                s += __ldcg(&g_part[((size_t)pp*Bn + bn)*Sn + bj]);
            float val = (s + EPSF) * __ldg(&g_po[((size_t)t*Bn + bn)*Sn + bj]);
            out_b[((size_t)t*Bn + bn)*Sn + bj] = val;       // unnormalized; fixed post-scan
            __stcg(&g_belT[(size_t)bj*Bn + bn], val);
            float ws = val;
            #pragma unroll
            for (int o = 16; o > 0; o >>= 1) ws += __shfl_xor_sync(0xffffffffu, ws, o);
            if (lane == 0) red[warp] = ws;
            __syncthreads();
            if (tid == 0) {
                float tot = 0.f;
                #pragma unroll
                for (int w = 0; w < 8; w++) tot += red[w];
                __stcg(&g_normAll[(t*2 + jh)*Bn + bn], tot);
            }
        }

        grid_sync_dev();
    }
}

// ---------------- post-scan: normalize out_b by per-(t,n) norms ----------------
__global__ void k_fix(float* __restrict__ out_b) {
    int tn = blockIdx.x;            // t*64 + n
    int t = tn >> 6, n = tn & 63;
    float inv = 1.f / (g_normAll[(t*2 + 0)*Bn + n] + g_normAll[(t*2 + 1)*Bn + n]);
    out_b[(size_t)tn*Sn + threadIdx.x] *= inv;
}

// ---------------- post-scan plan: logits, softmax over A, tau-weighted sum over H ----------------
#define HB 4
__global__ void __launch_bounds__(256)
k_plan(const float* __restrict__ value,
       const float* __restrict__ alpha_b,
       float* __restrict__ out_pi) {
    int n  = blockIdx.x;
    int hq = blockIdx.y;          // 0..7, handles h = hq*HB .. +3
    int tid = threadIdx.x;        // 256
    int tk = tid & 15;            // k
    int tg = tid >> 4;            // t-group of 4

    __shared__ float Vsh[HB][32][17];
    __shared__ float Bsh[64][33];
    __shared__ float Lsh[HB][64][17];

    float acc[HB][4];
    #pragma unroll
    for (int h = 0; h < HB; h++)
        #pragma unroll
        for (int a = 0; a < 4; a++) acc[h][a] = 0.f;

    const float* bbase = alpha_b + (size_t)n*Sn;

    for (int i0 = 0; i0 < Sn; i0 += 32) {
        #pragma unroll
        for (int q = 0; q < 8; q++) {                  // HB*32*16 = 2048 elems
            int e = tid + q*256;
            int ii = e & 31, rest = e >> 5;
            int kk2 = rest & 15, hh = rest >> 4;
            Vsh[hh][ii][kk2] =
                value[(((size_t)(hq*HB + hh)*Bn + n)*An + kk2)*Sn + i0 + ii];
        }
        #pragma unroll
        for (int q = 0; q < 8; q++) {                  // 64*32 = 2048 elems
            int e = tid + q*256; int ii = e & 31, tt = e >> 5;
            Bsh[tt][ii] = bbase[(size_t)tt*Bn*Sn + i0 + ii];
        }
        __syncthreads();
        for (int ii = 0; ii < 32; ii++) {
            float bv[4];
            #pragma unroll
            for (int a = 0; a < 4; a++) bv[a] = Bsh[tg*4 + a][ii];
            #pragma unroll
            for (int h = 0; h < HB; h++) {
                float vv = Vsh[h][ii][tk];
                #pragma unroll
                for (int a = 0; a < 4; a++) acc[h][a] = fmaf(bv[a], vv, acc[h][a]);
            }
        }
        __syncthreads();
    }

    #pragma unroll
    for (int h = 0; h < HB; h++)
        #pragma unroll
        for (int a = 0; a < 4; a++) Lsh[h][tg*4 + a][tk] = acc[h][a];
    __syncthreads();

    int hh = tid >> 6, t = tid & 63;
    float m = -1e30f;
    #pragma unroll
    for (int k = 0; k < An; k++) m = fmaxf(m, Lsh[hh][t][k]);
    float e[An]; float ssum = 0.f;
    #pragma unroll
    for (int k = 0; k < An; k++) { e[k] = expf(Lsh[hh][t][k] - m); ssum += e[k]; }
    float w = g_taupdf[hq*HB + hh] / ssum;
    #pragma unroll
    for (int k = 0; k < An; k++)
        atomicAdd(&out_pi[((size_t)t*Bn + n)*An + k], e[k] * w);
}

// ---------------- launch ----------------
extern "C" void kernel_launch(void* const* d_in, const int* in_sizes, int n_in,
                              void* d_out, int out_size) {
    const float* logp_o = (const float*)d_in[0];
    const float* logp_u = (const float*)d_in[1];
    const float* value  = (const float*)d_in[2];
    const float* b      = (const float*)d_in[3];
    const float* u      = (const float*)d_in[4];
    const float* v      = (const float*)d_in[5];
    const float* tau    = (const float*)d_in[6];

    float* out    = (float*)d_out;
    float* out_b  = out;                       // [T,B,S]
    float* out_pi = out + (size_t)Tn*Bn*Sn;    // [T,B,A]

    static int smem_set = 0;
    if (!smem_set) {
        cudaFuncSetAttribute(k_scan, cudaFuncAttributeMaxDynamicSharedMemorySize,
                             SMEM_F * (int)sizeof(float));
        smem_set = 1;
    }

    k_pv<<<An, 64>>>(u, v);
    k_gram<<<Sn, 128>>>(u);
    k_trans8<<<dim3(Sn/8, An), 512>>>();
    k_taupdf<<<1, 32>>>(tau);
    k_alpha_a<<<(Tn*Bn + 127)/128, 128>>>(logp_u);
    k_po<<<(Tn*Bn*Sn)/512, 512>>>(logp_o);
    k_init_bel<<<Bn, Sn>>>(b);

    k_scan<<<NUNITS, 256, SMEM_F * (int)sizeof(float)>>>(out_b);

    k_fix<<<Tn*Bn, Sn>>>(out_b);
    cudaMemsetAsync(out_pi, 0, sizeof(float)*(size_t)Tn*Bn*An);
    k_plan<<<dim3(Bn, Hn/HB), 256>>>(value, out_b, out_pi);
}

// round 10
// speedup vs baseline: 3.3317x; 1.0895x over previous
#include <cuda_runtime.h>
#include <cuda_fp16.h>
#include <math.h>
#include <stdint.h>

#define Tn 64
#define Bn 64
#define Sn 512
#define An 16
#define Rn 64
#define Hn 32
#define EPSF 1e-6f

#define ISL 2            // i-slices per (j-tile, k)
#define NP  (An*ISL)     // 32 partial slabs
#define TJ 128
#define ILEN (Sn/ISL)    // 256
#define NUNITS 128       // persistent CTAs = 4 jt * 16 k * 2 isl

// dynamic smem layout (bytes)
#define TSL_B   65536            // T slab: 256 i x 128 j fp16 fragments
#define CSH_STRIDE 72            // half2 words per i-pair row (72*4B; 72%32==8 -> bank-safe)
#define CSH_B   (128*CSH_STRIDE*4)   // 36864
#define SMEM_B  (TSL_B + CSH_B + 256 + 256)

// ---------------- scratch (device globals; no allocation) ----------------
// T permuted into m16n8k16 B-fragment layout: [k][i16][j8][lane][reg][half], fp16
__device__ __align__(16) unsigned short g_transPh[(size_t)An*Sn*Sn];  // 8.4 MB
__device__ float g_G[Sn*Sn];                                  // 1 MB
__device__ float g_p[An*Sn];
__device__ float g_taupdf[Hn];
__device__ float g_alpha_a[(size_t)Tn*Bn*An];
__device__ __align__(16) float g_belT[Sn*Bn];                 // belief (unnormalized), [i][n]
__device__ __align__(16) float g_part[(size_t)NP*Bn*Sn];      // 4 MB partials
__device__ __align__(16) float g_po[(size_t)Tn*Bn*Sn];        // exp(logp_o), 8 MB
__device__ float g_normAll[Tn*2*Bn];                          // per (t, jhalf, n) norm partials

__device__ int          g_bar_count;
__device__ volatile int g_bar_gen;

// ---------------- helpers ----------------
__device__ __forceinline__ void mma_f16(float& c0, float& c1, float& c2, float& c3,
                                        uint32_t a0, uint32_t a1, uint32_t a2, uint32_t a3,
                                        uint32_t b0, uint32_t b1) {
    asm volatile("mma.sync.aligned.m16n8k16.row.col.f32.f16.f16.f32 "
                 "{%0,%1,%2,%3},{%4,%5,%6,%7},{%8,%9},{%0,%1,%2,%3};\n"
                 : "+f"(c0), "+f"(c1), "+f"(c2), "+f"(c3)
                 : "r"(a0), "r"(a1), "r"(a2), "r"(a3), "r"(b0), "r"(b1));
}

// ---------------- precompute: v_norm and p[k][i] = u[i].v_hat[k] ----------------
__global__ void k_pv(const float* __restrict__ u, const float* __restrict__ v) {
    int k = blockIdx.x;
    int t = threadIdx.x;  // 64 threads
    __shared__ float vn[Rn];
    __shared__ float sb[64];
    float x = v[k*Rn + t];
    sb[t] = x * x;
    __syncthreads();
    for (int s = 32; s > 0; s >>= 1) { if (t < s) sb[t] += sb[t+s]; __syncthreads(); }
    vn[t] = x * rsqrtf(sb[0]);
    __syncthreads();
    for (int i = t; i < Sn; i += 64) {
        float s = 0.f;
        #pragma unroll
        for (int r = 0; r < Rn; r++) s += u[i*Rn + r] * vn[r];
        g_p[k*Sn + i] = s;
    }
}

// ---------------- precompute: G[i][j] = u[i].u[j] ----------------
__global__ void k_gram(const float* __restrict__ u) {
    int i = blockIdx.x;
    int tid = threadIdx.x;  // 128
    __shared__ float ui[Rn];
    if (tid < Rn) ui[tid] = u[i*Rn + tid];
    __syncthreads();
    for (int j = tid; j < Sn; j += 128) {
        float s = 0.f;
        #pragma unroll
        for (int r = 0; r < Rn; r++) s += u[j*Rn + r] * ui[r];
        g_G[i*Sn + j] = s;
    }
}

// ---------------- precompute: transition softmax -> fp16 m16n8k16 B-fragment layout ----------------
// one block per (i16, k): 16 row-softmaxes, then contiguous 16 KB fragment-block store
__global__ void k_trans16() {
    int ib = blockIdx.x, k = blockIdx.y;   // ib: 0..31
    int j = threadIdx.x;  // 512
    __shared__ float red[512];
    __shared__ __align__(16) unsigned short stage[8192];
    float pkj = g_p[k*Sn + j];

    #pragma unroll 1
    for (int r = 0; r < 16; r++) {
        int i = ib*16 + r;
        float w = g_G[i*Sn + j] - 2.f * g_p[k*Sn + i] * pkj;
        red[j] = w; __syncthreads();
        for (int s = 256; s > 0; s >>= 1) { if (j < s) red[j] = fmaxf(red[j], red[j+s]); __syncthreads(); }
        float m = red[0]; __syncthreads();
        float e = expf(w - m);
        red[j] = e; __syncthreads();
        for (int s = 256; s > 0; s >>= 1) { if (j < s) red[j] += red[j+s]; __syncthreads(); }
        float pr = e * (1.f / red[0]);
        // fragment pos: lane = (j&7)*4 + ((r&7)>>1); reg = r>>3; half = r&1
        int lane = (j & 7)*4 + ((r & 7) >> 1);
        int idx = (((j >> 3)*32 + lane)*2 + (r >> 3))*2 + (r & 1);
        stage[idx] = __half_as_ushort(__float2half_rn(pr));
        __syncthreads();
    }

    const uint4* s4 = reinterpret_cast<const uint4*>(stage);
    uint4* d4 = reinterpret_cast<uint4*>(g_transPh + (size_t)(k*32 + ib)*8192);
    d4[j]       = s4[j];
    d4[j + 512] = s4[j + 512];
}

// ---------------- precompute: normalized Poisson pdf over horizon ----------------
__global__ void k_taupdf(const float* __restrict__ tau) {
    int t = threadIdx.x;  // 32
    float rate = log1pf(expf(tau[0]));   // softplus
    float kk = (float)(t + 1);
    float lp = kk * logf(rate) - rate - lgammaf(kk + 1.f);
    float p = expf(lp);
    float s = p;
    #pragma unroll
    for (int o = 16; o > 0; o >>= 1) s += __shfl_xor_sync(0xffffffffu, s, o);
    g_taupdf[t] = p / s;
}

// ---------------- precompute: alpha_a = softmax(logp_u) over A ----------------
__global__ void k_alpha_a(const float* __restrict__ logp_u) {
    int idx = blockIdx.x * blockDim.x + threadIdx.x;
    if (idx >= Tn*Bn) return;
    const float* r = logp_u + (size_t)idx*An;
    float m = -1e30f;
    #pragma unroll
    for (int k = 0; k < An; k++) m = fmaxf(m, r[k]);
    float e[An]; float s = 0.f;
    #pragma unroll
    for (int k = 0; k < An; k++) { e[k] = expf(r[k] - m); s += e[k]; }
    float inv = 1.f / s;
    #pragma unroll
    for (int k = 0; k < An; k++) g_alpha_a[(size_t)idx*An + k] = e[k] * inv;
}

// ---------------- precompute: po = exp(logp_o) ----------------
__global__ void k_po(const float* __restrict__ logp_o) {
    size_t idx = (size_t)blockIdx.x * 512 + threadIdx.x;
    g_po[idx] = expf(logp_o[idx]);
}

// ---------------- init belief (transposed) ----------------
__global__ void k_init_bel(const float* __restrict__ b) {
    int n = blockIdx.x, j = threadIdx.x;  // (Bn, Sn)
    g_belT[j*Bn + n] = b[n*Sn + j];
}

// ---------------- grid-wide barrier (all NUNITS CTAs co-resident) ----------------
__device__ __forceinline__ void grid_sync_dev() {
    __syncthreads();
    if (threadIdx.x == 0) {
        int old = g_bar_gen;
        __threadfence();
        int t = atomicAdd(&g_bar_count, 1);
        if (t == NUNITS - 1) {
            g_bar_count = 0;
            __threadfence();
            g_bar_gen = old + 1;
        } else {
            while (g_bar_gen == old) __nanosleep(64);
        }
    }
    __syncthreads();
    __threadfence();
}

// ---------------- fused persistent scan: SMEM-resident fp16 T, 64 steps ----------------
__global__ void __launch_bounds__(256, 1)
k_scan(float* __restrict__ out_b) {
    extern __shared__ char smem[];
    unsigned short* Tsl = reinterpret_cast<unsigned short*>(smem);           // 64 KB
    uint32_t* csh = reinterpret_cast<uint32_t*>(smem + TSL_B);               // [128][72] half2 words
    float*    ash = reinterpret_cast<float*>(smem + TSL_B + CSH_B);          // 64
    float*    red = ash + 64;                                                // 64

    int tid  = threadIdx.x;            // 256
    int unit = blockIdx.x;             // 0..127
    int jt   = unit & 3;
    int kk   = (unit >> 2) & 15;
    int isl  = unit >> 6;              // 0..1
    int j0   = jt * TJ;
    int i0   = isl * ILEN;             // 0 or 256
    int lane = tid & 31;
    int warp = tid >> 5;
    int gid  = lane >> 2;              // 0..7
    int tig  = lane & 3;               // 0..3
    int mw   = warp & 1;               // 2 warps over M (n)
    int nw   = warp >> 1;              // 4 warps over N (j)
    int nwb  = mw * 32;                // warp n base within 64
    int p    = kk*ISL + isl;

    // phase-B identity (all 128 CTAs participate)
    int bn = unit >> 1;                // batch n
    int jh = unit & 1;                 // j half
    int bj = jh*256 + tid;             // j column

    // ---- one-time: load this CTA's permuted fp16 T slab into SMEM (64 KB) ----
    {
        const uint4* src = reinterpret_cast<const uint4*>(g_transPh);
        uint4* dst = reinterpret_cast<uint4*>(Tsl);
        #pragma unroll
        for (int q = 0; q < 16; q++) {             // 4096 uint4 / 256 thr
            int f = tid + q*256;
            int blk = f >> 4, r = f & 15;          // blk = ib_l*16 + j8_l
            int ib_l = blk >> 4, j8_l = blk & 15;
            dst[f] = src[(size_t)((kk*32 + isl*16 + ib_l)*64 + jt*16 + j8_l)*16 + r];
        }
    }
    const uint2* Tsl2 = reinterpret_cast<const uint2*>(Tsl);

    int n4  = (tid & 15) * 4;          // staging n base
    int ipb = tid >> 4;                // staging i-pair base (stride 16)
    __syncthreads();

    for (int t = 0; t < Tn; t++) {
        // ---------- phase A: stage fp16 coefficient tile (inv-norm folded), pure MMA ----------
        if (tid < Bn) {
            float a = g_alpha_a[((size_t)t*Bn + tid)*An + kk];
            if (t > 0) {
                float q0 = __ldcg(&g_normAll[((t-1)*2 + 0)*Bn + tid]);
                float q1 = __ldcg(&g_normAll[((t-1)*2 + 1)*Bn + tid]);
                a *= 1.f / (q0 + q1);
            }
            ash[tid] = a;
        }
        __syncthreads();
        {
            float4 a4 = *reinterpret_cast<const float4*>(&ash[n4]);
            #pragma unroll
            for (int q = 0; q < 8; q++) {
                int ip = ipb + q*16;               // i-pair 0..127
                int i = i0 + 2*ip;
                float4 e4 = __ldcg(reinterpret_cast<const float4*>(
                                   &g_belT[(size_t)i*Bn + n4]));
                float4 o4 = __ldcg(reinterpret_cast<const float4*>(
                                   &g_belT[(size_t)(i+1)*Bn + n4]));
                __half2 h0 = __float22half2_rn(make_float2(a4.x*e4.x, a4.x*o4.x));
                __half2 h1 = __float22half2_rn(make_float2(a4.y*e4.y, a4.y*o4.y));
                __half2 h2 = __float22half2_rn(make_float2(a4.z*e4.z, a4.z*o4.z));
                __half2 h3 = __float22half2_rn(make_float2(a4.w*e4.w, a4.w*o4.w));
                uint4 o;
                o.x = *reinterpret_cast<uint32_t*>(&h0);
                o.y = *reinterpret_cast<uint32_t*>(&h1);
                o.z = *reinterpret_cast<uint32_t*>(&h2);
                o.w = *reinterpret_cast<uint32_t*>(&h3);
                *reinterpret_cast<uint4*>(&csh[ip*CSH_STRIDE + n4]) = o;
            }
        }
        __syncthreads();

        float c[2][4][4];
        #pragma unroll
        for (int mt = 0; mt < 2; mt++)
            #pragma unroll
            for (int nt = 0; nt < 4; nt++)
                #pragma unroll
                for (int r = 0; r < 4; r++) c[mt][nt][r] = 0.f;

        #pragma unroll 4
        for (int ks = 0; ks < 16; ks++) {          // 16 k-steps of 16 i
            int r0 = ks*8;                         // i-pair row base
            uint32_t a[2][4];
            #pragma unroll
            for (int mt = 0; mt < 2; mt++) {
                int n0 = nwb + mt*16;
                a[mt][0] = csh[(r0 + tig    )*CSH_STRIDE + n0 + gid    ];
                a[mt][1] = csh[(r0 + tig    )*CSH_STRIDE + n0 + gid + 8];
                a[mt][2] = csh[(r0 + tig + 4)*CSH_STRIDE + n0 + gid    ];
                a[mt][3] = csh[(r0 + tig + 4)*CSH_STRIDE + n0 + gid + 8];
            }
            #pragma unroll
            for (int nt = 0; nt < 4; nt++) {
                uint2 bf = Tsl2[(ks*16 + nw*4 + nt)*32 + lane];
                #pragma unroll
                for (int mt = 0; mt < 2; mt++)
                    mma_f16(c[mt][nt][0], c[mt][nt][1], c[mt][nt][2], c[mt][nt][3],
                            a[mt][0], a[mt][1], a[mt][2], a[mt][3], bf.x, bf.y);
            }
        }

        // write partial slab
        #pragma unroll
        for (int mt = 0; mt < 2; mt++) {
            int n_lo = nwb + mt*16 + gid;
            #pragma unroll
            for (int nt = 0; nt < 4; nt++) {
                int jcol = j0 + nw*32 + nt*8 + 2*tig;
                float* op0 = &g_part[((size_t)p*Bn + n_lo)*Sn + jcol];
                float* op1 = &g_part[((size_t)p*Bn + n_lo + 8)*Sn + jcol];
                __stcg(reinterpret_cast<float2*>(op0), make_float2(c[mt][nt][0], c[mt][nt][1]));
                __stcg(reinterpret_cast<float2*>(op1), make_float2(c[mt][nt][2], c[mt][nt][3]));
            }
        }

        grid_sync_dev();

        // ---------- phase B: reduce partials, (s+eps)*po, deferred-norm belief ----------
        {
            float s = 0.f;
            #pragma unroll 8
            for (int pp = 0; pp < NP; pp++)
                s += __ldcg(&g_part[((size_t)pp*Bn + bn)*Sn + bj]);
            float val = (s + EPSF) * __ldg(&g_po[((size_t)t*Bn + bn)*Sn + bj]);
            out_b[((size_t)t*Bn + bn)*Sn + bj] = val;       // unnormalized; fixed post-scan
            __stcg(&g_belT[(size_t)bj*Bn + bn], val);
            float ws = val;
            #pragma unroll
            for (int o = 16; o > 0; o >>= 1) ws += __shfl_xor_sync(0xffffffffu, ws, o);
            if (lane == 0) red[warp] = ws;
            __syncthreads();
            if (tid == 0) {
                float tot = 0.f;
                #pragma unroll
                for (int w = 0; w < 8; w++) tot += red[w];
                __stcg(&g_normAll[(t*2 + jh)*Bn + bn], tot);
            }
        }

        grid_sync_dev();
    }
}

// ---------------- post-scan: normalize out_b by per-(t,n) norms ----------------
__global__ void k_fix(float* __restrict__ out_b) {
    int tn = blockIdx.x;            // t*64 + n
    int t = tn >> 6, n = tn & 63;
    float inv = 1.f / (g_normAll[(t*2 + 0)*Bn + n] + g_normAll[(t*2 + 1)*Bn + n]);
    out_b[(size_t)tn*Sn + threadIdx.x] *= inv;
}

// ---------------- post-scan plan: logits, softmax over A, tau-weighted sum over H ----------------
#define HB 4
__global__ void __launch_bounds__(256)
k_plan(const float* __restrict__ value,
       const float* __restrict__ alpha_b,
       float* __restrict__ out_pi) {
    int n  = blockIdx.x;
    int hq = blockIdx.y;          // 0..7, handles h = hq*HB .. +3
    int tid = threadIdx.x;        // 256
    int tk = tid & 15;            // k
    int tg = tid >> 4;            // t-group of 4

    __shared__ float Vsh[HB][32][17];
    __shared__ float Bsh[64][33];
    __shared__ float Lsh[HB][64][17];

    float acc[HB][4];
    #pragma unroll
    for (int h = 0; h < HB; h++)
        #pragma unroll
        for (int a = 0; a < 4; a++) acc[h][a] = 0.f;

    const float* bbase = alpha_b + (size_t)n*Sn;

    for (int i0 = 0; i0 < Sn; i0 += 32) {
        #pragma unroll
        for (int q = 0; q < 8; q++) {                  // HB*32*16 = 2048 elems
            int e = tid + q*256;
            int ii = e & 31, rest = e >> 5;
            int kk2 = rest & 15, hh = rest >> 4;
            Vsh[hh][ii][kk2] =
                value[(((size_t)(hq*HB + hh)*Bn + n)*An + kk2)*Sn + i0 + ii];
        }
        #pragma unroll
        for (int q = 0; q < 8; q++) {                  // 64*32 = 2048 elems
            int e = tid + q*256; int ii = e & 31, tt = e >> 5;
            Bsh[tt][ii] = bbase[(size_t)tt*Bn*Sn + i0 + ii];
        }
        __syncthreads();
        for (int ii = 0; ii < 32; ii++) {
            float bv[4];
            #pragma unroll
            for (int a = 0; a < 4; a++) bv[a] = Bsh[tg*4 + a][ii];
            #pragma unroll
            for (int h = 0; h < HB; h++) {
                float vv = Vsh[h][ii][tk];
                #pragma unroll
                for (int a = 0; a < 4; a++) acc[h][a] = fmaf(bv[a], vv, acc[h][a]);
            }
        }
        __syncthreads();
    }

    #pragma unroll
    for (int h = 0; h < HB; h++)
        #pragma unroll
        for (int a = 0; a < 4; a++) Lsh[h][tg*4 + a][tk] = acc[h][a];
    __syncthreads();

    int hh = tid >> 6, t = tid & 63;
    float m = -1e30f;
    #pragma unroll
    for (int k = 0; k < An; k++) m = fmaxf(m, Lsh[hh][t][k]);
    float e[An]; float ssum = 0.f;
    #pragma unroll
    for (int k = 0; k < An; k++) { e[k] = expf(Lsh[hh][t][k] - m); ssum += e[k]; }
    float w = g_taupdf[hq*HB + hh] / ssum;
    #pragma unroll
    for (int k = 0; k < An; k++)
        atomicAdd(&out_pi[((size_t)t*Bn + n)*An + k], e[k] * w);
}

// ---------------- launch ----------------
extern "C" void kernel_launch(void* const* d_in, const int* in_sizes, int n_in,
                              void* d_out, int out_size) {
    const float* logp_o = (const float*)d_in[0];
    const float* logp_u = (const float*)d_in[1];
    const float* value  = (const float*)d_in[2];
    const float* b      = (const float*)d_in[3];
    const float* u      = (const float*)d_in[4];
    const float* v      = (const float*)d_in[5];
    const float* tau    = (const float*)d_in[6];

    float* out    = (float*)d_out;
    float* out_b  = out;                       // [T,B,S]
    float* out_pi = out + (size_t)Tn*Bn*Sn;    // [T,B,A]

    static int smem_set = 0;
    if (!smem_set) {
        cudaFuncSetAttribute(k_scan, cudaFuncAttributeMaxDynamicSharedMemorySize, SMEM_B);
        smem_set = 1;
    }

    k_pv<<<An, 64>>>(u, v);
    k_gram<<<Sn, 128>>>(u);
    k_trans16<<<dim3(Sn/16, An), 512>>>();
    k_taupdf<<<1, 32>>>(tau);
    k_alpha_a<<<(Tn*Bn + 127)/128, 128>>>(logp_u);
    k_po<<<(Tn*Bn*Sn)/512, 512>>>(logp_o);
    k_init_bel<<<Bn, Sn>>>(b);

    k_scan<<<NUNITS, 256, SMEM_B>>>(out_b);

    k_fix<<<Tn*Bn, Sn>>>(out_b);
    cudaMemsetAsync(out_pi, 0, sizeof(float)*(size_t)Tn*Bn*An);
    k_plan<<<dim3(Bn, Hn/HB), 256>>>(value, out_b, out_pi);
}

// round 11
// speedup vs baseline: 3.3682x; 1.0109x over previous
#include <cuda_runtime.h>
#include <cuda_fp16.h>
#include <math.h>
#include <stdint.h>

#define Tn 64
#define Bn 64
#define Sn 512
#define An 16
#define Rn 64
#define Hn 32
#define EPSF 1e-6f

#define ISL 2            // i-slices per (j-tile, k)
#define TJ 128
#define ILEN (Sn/ISL)    // 256
#define NUNITS 128       // persistent CTAs = 4 jt * 16 k * 2 isl

// dynamic smem layout (bytes)
#define TSL_B   65536            // T slab: 256 i x 128 j fp16 fragments
#define CSH_STRIDE 72            // half2 words per i-pair row (72*4B; 72%32==8 -> bank-safe)
#define CSH_B   (128*CSH_STRIDE*4)   // 36864
#define SMEM_B  (TSL_B + CSH_B + 256 + 256)

// ---------------- scratch (device globals; no allocation) ----------------
// T permuted into m16n8k16 B-fragment layout: [k][i16][j8][lane][reg][half], fp16
__device__ __align__(16) unsigned short g_transPh[(size_t)An*Sn*Sn];  // 8.4 MB
__device__ float g_G[Sn*Sn];                                  // 1 MB
__device__ float g_p[An*Sn];
__device__ float g_taupdf[Hn];
__device__ float g_alpha_a[(size_t)Tn*Bn*An];
__device__ __align__(16) float g_belT[Sn*Bn];                 // belief (unnormalized), [i][n]
__device__ __align__(16) float g_acc[Bn*Sn];                  // single RED-accumulated slab, 128 KB
__device__ __align__(16) float g_po[(size_t)Tn*Bn*Sn];        // exp(logp_o), 8 MB
__device__ float g_normAll[Tn*2*Bn];                          // per (t, jhalf, n) norm partials

__device__ int          g_bar_count;
__device__ volatile int g_bar_gen;

// ---------------- helpers ----------------
__device__ __forceinline__ uint32_t f2tf32(float x) {
    uint32_t u;
    asm("cvt.rna.tf32.f32 %0, %1;" : "=r"(u) : "f"(x));
    return u;
}

__device__ __forceinline__ void red_add(float* p, float v) {
    asm volatile("red.global.add.f32 [%0], %1;" :: "l"(p), "f"(v) : "memory");
}

__device__ __forceinline__ void mma_f16(float& c0, float& c1, float& c2, float& c3,
                                        uint32_t a0, uint32_t a1, uint32_t a2, uint32_t a3,
                                        uint32_t b0, uint32_t b1) {
    asm volatile("mma.sync.aligned.m16n8k16.row.col.f32.f16.f16.f32 "
                 "{%0,%1,%2,%3},{%4,%5,%6,%7},{%8,%9},{%0,%1,%2,%3};\n"
                 : "+f"(c0), "+f"(c1), "+f"(c2), "+f"(c3)
                 : "r"(a0), "r"(a1), "r"(a2), "r"(a3), "r"(b0), "r"(b1));
}

__device__ __forceinline__ void mma_tf32(float& c0, float& c1, float& c2, float& c3,
                                         uint32_t a0, uint32_t a1, uint32_t a2, uint32_t a3,
                                         uint32_t b0, uint32_t b1) {
    asm volatile("mma.sync.aligned.m16n8k8.row.col.f32.tf32.tf32.f32 "
                 "{%0,%1,%2,%3},{%4,%5,%6,%7},{%8,%9},{%0,%1,%2,%3};\n"
                 : "+f"(c0), "+f"(c1), "+f"(c2), "+f"(c3)
                 : "r"(a0), "r"(a1), "r"(a2), "r"(a3), "r"(b0), "r"(b1));
}

// ---------------- precompute: v_norm and p[k][i] = u[i].v_hat[k] ----------------
__global__ void k_pv(const float* __restrict__ u, const float* __restrict__ v) {
    int k = blockIdx.x;
    int t = threadIdx.x;  // 64 threads
    __shared__ float vn[Rn];
    __shared__ float sb[64];
    float x = v[k*Rn + t];
    sb[t] = x * x;
    __syncthreads();
    for (int s = 32; s > 0; s >>= 1) { if (t < s) sb[t] += sb[t+s]; __syncthreads(); }
    vn[t] = x * rsqrtf(sb[0]);
    __syncthreads();
    for (int i = t; i < Sn; i += 64) {
        float s = 0.f;
        #pragma unroll
        for (int r = 0; r < Rn; r++) s += u[i*Rn + r] * vn[r];
        g_p[k*Sn + i] = s;
    }
}

// ---------------- precompute: G[i][j] = u[i].u[j] ----------------
__global__ void k_gram(const float* __restrict__ u) {
    int i = blockIdx.x;
    int tid = threadIdx.x;  // 128
    __shared__ float ui[Rn];
    if (tid < Rn) ui[tid] = u[i*Rn + tid];
    __syncthreads();
    for (int j = tid; j < Sn; j += 128) {
        float s = 0.f;
        #pragma unroll
        for (int r = 0; r < Rn; r++) s += u[j*Rn + r] * ui[r];
        g_G[i*Sn + j] = s;
    }
}

// ---------------- precompute: transition softmax -> fp16 m16n8k16 B-fragment layout ----------------
__global__ void k_trans16() {
    int ib = blockIdx.x, k = blockIdx.y;   // ib: 0..31
    int j = threadIdx.x;  // 512
    __shared__ float red[512];
    __shared__ __align__(16) unsigned short stage[8192];
    float pkj = g_p[k*Sn + j];

    #pragma unroll 1
    for (int r = 0; r < 16; r++) {
        int i = ib*16 + r;
        float w = g_G[i*Sn + j] - 2.f * g_p[k*Sn + i] * pkj;
        red[j] = w; __syncthreads();
        for (int s = 256; s > 0; s >>= 1) { if (j < s) red[j] = fmaxf(red[j], red[j+s]); __syncthreads(); }
        float m = red[0]; __syncthreads();
        float e = expf(w - m);
        red[j] = e; __syncthreads();
        for (int s = 256; s > 0; s >>= 1) { if (j < s) red[j] += red[j+s]; __syncthreads(); }
        float pr = e * (1.f / red[0]);
        int lane = (j & 7)*4 + ((r & 7) >> 1);
        int idx = (((j >> 3)*32 + lane)*2 + (r >> 3))*2 + (r & 1);
        stage[idx] = __half_as_ushort(__float2half_rn(pr));
        __syncthreads();
    }

    const uint4* s4 = reinterpret_cast<const uint4*>(stage);
    uint4* d4 = reinterpret_cast<uint4*>(g_transPh + (size_t)(k*32 + ib)*8192);
    d4[j]       = s4[j];
    d4[j + 512] = s4[j + 512];
}

// ---------------- precompute: normalized Poisson pdf over horizon ----------------
__global__ void k_taupdf(const float* __restrict__ tau) {
    int t = threadIdx.x;  // 32
    float rate = log1pf(expf(tau[0]));   // softplus
    float kk = (float)(t + 1);
    float lp = kk * logf(rate) - rate - lgammaf(kk + 1.f);
    float p = expf(lp);
    float s = p;
    #pragma unroll
    for (int o = 16; o > 0; o >>= 1) s += __shfl_xor_sync(0xffffffffu, s, o);
    g_taupdf[t] = p / s;
}

// ---------------- precompute: alpha_a = softmax(logp_u) over A ----------------
__global__ void k_alpha_a(const float* __restrict__ logp_u) {
    int idx = blockIdx.x * blockDim.x + threadIdx.x;
    if (idx >= Tn*Bn) return;
    const float* r = logp_u + (size_t)idx*An;
    float m = -1e30f;
    #pragma unroll
    for (int k = 0; k < An; k++) m = fmaxf(m, r[k]);
    float e[An]; float s = 0.f;
    #pragma unroll
    for (int k = 0; k < An; k++) { e[k] = expf(r[k] - m); s += e[k]; }
    float inv = 1.f / s;
    #pragma unroll
    for (int k = 0; k < An; k++) g_alpha_a[(size_t)idx*An + k] = e[k] * inv;
}

// ---------------- precompute: po = exp(logp_o) ----------------
__global__ void k_po(const float* __restrict__ logp_o) {
    size_t idx = (size_t)blockIdx.x * 512 + threadIdx.x;
    g_po[idx] = expf(logp_o[idx]);
}

// ---------------- init belief (transposed) + zero the RED slab ----------------
__global__ void k_init_bel(const float* __restrict__ b) {
    int n = blockIdx.x, j = threadIdx.x;  // (Bn, Sn)
    g_belT[j*Bn + n] = b[n*Sn + j];
    g_acc[n*Sn + j] = 0.f;
}

// ---------------- grid-wide barrier (all NUNITS CTAs co-resident) ----------------
__device__ __forceinline__ void grid_sync_dev() {
    __syncthreads();
    if (threadIdx.x == 0) {
        int old = g_bar_gen;
        __threadfence();
        int t = atomicAdd(&g_bar_count, 1);
        if (t == NUNITS - 1) {
            g_bar_count = 0;
            __threadfence();
            g_bar_gen = old + 1;
        } else {
            while (g_bar_gen == old) __nanosleep(64);
        }
    }
    __syncthreads();
    __threadfence();
}

// ---------------- fused persistent scan: SMEM-resident fp16 T, RED slab, 64 steps ----------------
__global__ void __launch_bounds__(256, 1)
k_scan(float* __restrict__ out_b) {
    extern __shared__ char smem[];
    unsigned short* Tsl = reinterpret_cast<unsigned short*>(smem);           // 64 KB
    uint32_t* csh = reinterpret_cast<uint32_t*>(smem + TSL_B);               // [128][72] half2 words
    float*    ash = reinterpret_cast<float*>(smem + TSL_B + CSH_B);          // 64
    float*    red = ash + 64;                                                // 64

    int tid  = threadIdx.x;            // 256
    int unit = blockIdx.x;             // 0..127
    int jt   = unit & 3;
    int kk   = (unit >> 2) & 15;
    int isl  = unit >> 6;              // 0..1
    int j0   = jt * TJ;
    int i0   = isl * ILEN;             // 0 or 256
    int lane = tid & 31;
    int warp = tid >> 5;
    int gid  = lane >> 2;              // 0..7
    int tig  = lane & 3;               // 0..3
    int mw   = warp & 1;               // 2 warps over M (n)
    int nw   = warp >> 1;              // 4 warps over N (j)
    int nwb  = mw * 32;                // warp n base within 64

    // phase-B identity (all 128 CTAs participate)
    int bn = unit >> 1;                // batch n
    int jh = unit & 1;                 // j half
    int bj = jh*256 + tid;             // j column

    // ---- one-time: load this CTA's permuted fp16 T slab into SMEM (64 KB) ----
    {
        const uint4* src = reinterpret_cast<const uint4*>(g_transPh);
        uint4* dst = reinterpret_cast<uint4*>(Tsl);
        #pragma unroll
        for (int q = 0; q < 16; q++) {             // 4096 uint4 / 256 thr
            int f = tid + q*256;
            int blk = f >> 4, r = f & 15;          // blk = ib_l*16 + j8_l
            int ib_l = blk >> 4, j8_l = blk & 15;
            dst[f] = src[(size_t)((kk*32 + isl*16 + ib_l)*64 + jt*16 + j8_l)*16 + r];
        }
    }
    const uint2* Tsl2 = reinterpret_cast<const uint2*>(Tsl);

    int n4  = (tid & 15) * 4;          // staging n base
    int ipb = tid >> 4;                // staging i-pair base (stride 16)
    __syncthreads();

    for (int t = 0; t < Tn; t++) {
        // ---------- phase A: stage fp16 coefficient tile (inv-norm folded), pure MMA ----------
        if (tid < Bn) {
            float a = g_alpha_a[((size_t)t*Bn + tid)*An + kk];
            if (t > 0) {
                float q0 = __ldcg(&g_normAll[((t-1)*2 + 0)*Bn + tid]);
                float q1 = __ldcg(&g_normAll[((t-1)*2 + 1)*Bn + tid]);
                a *= 1.f / (q0 + q1);
            }
            ash[tid] = a;
        }
        __syncthreads();
        {
            float4 a4 = *reinterpret_cast<const float4*>(&ash[n4]);
            #pragma unroll
            for (int q = 0; q < 8; q++) {
                int ip = ipb + q*16;               // i-pair 0..127
                int i = i0 + 2*ip;
                float4 e4 = __ldcg(reinterpret_cast<const float4*>(
                                   &g_belT[(size_t)i*Bn + n4]));
                float4 o4 = __ldcg(reinterpret_cast<const float4*>(
                                   &g_belT[(size_t)(i+1)*Bn + n4]));
                __half2 h0 = __float22half2_rn(make_float2(a4.x*e4.x, a4.x*o4.x));
                __half2 h1 = __float22half2_rn(make_float2(a4.y*e4.y, a4.y*o4.y));
                __half2 h2 = __float22half2_rn(make_float2(a4.z*e4.z, a4.z*o4.z));
                __half2 h3 = __float22half2_rn(make_float2(a4.w*e4.w, a4.w*o4.w));
                uint4 o;
                o.x = *reinterpret_cast<uint32_t*>(&h0);
                o.y = *reinterpret_cast<uint32_t*>(&h1);
                o.z = *reinterpret_cast<uint32_t*>(&h2);
                o.w = *reinterpret_cast<uint32_t*>(&h3);
                *reinterpret_cast<uint4*>(&csh[ip*CSH_STRIDE + n4]) = o;
            }
        }
        __syncthreads();

        float c[2][4][4];
        #pragma unroll
        for (int mt = 0; mt < 2; mt++)
            #pragma unroll
            for (int nt = 0; nt < 4; nt++)
                #pragma unroll
                for (int r = 0; r < 4; r++) c[mt][nt][r] = 0.f;

        #pragma unroll 4
        for (int ks = 0; ks < 16; ks++) {          // 16 k-steps of 16 i
            int r0 = ks*8;                         // i-pair row base
            uint32_t a[2][4];
            #pragma unroll
            for (int mt = 0; mt < 2; mt++) {
                int n0 = nwb + mt*16;
                a[mt][0] = csh[(r0 + tig    )*CSH_STRIDE + n0 + gid    ];
                a[mt][1] = csh[(r0 + tig    )*CSH_STRIDE + n0 + gid + 8];
                a[mt][2] = csh[(r0 + tig + 4)*CSH_STRIDE + n0 + gid    ];
                a[mt][3] = csh[(r0 + tig + 4)*CSH_STRIDE + n0 + gid + 8];
            }
            #pragma unroll
            for (int nt = 0; nt < 4; nt++) {
                uint2 bf = Tsl2[(ks*16 + nw*4 + nt)*32 + lane];
                #pragma unroll
                for (int mt = 0; mt < 2; mt++)
                    mma_f16(c[mt][nt][0], c[mt][nt][1], c[mt][nt][2], c[mt][nt][3],
                            a[mt][0], a[mt][1], a[mt][2], a[mt][3], bf.x, bf.y);
            }
        }

        // accumulate partial slab via L2 atomics (32 CTAs add per address)
        #pragma unroll
        for (int mt = 0; mt < 2; mt++) {
            int n_lo = nwb + mt*16 + gid;
            #pragma unroll
            for (int nt = 0; nt < 4; nt++) {
                int jcol = j0 + nw*32 + nt*8 + 2*tig;
                float* a0 = &g_acc[n_lo*Sn + jcol];
                float* a1 = &g_acc[(n_lo + 8)*Sn + jcol];
                red_add(a0,     c[mt][nt][0]);
                red_add(a0 + 1, c[mt][nt][1]);
                red_add(a1,     c[mt][nt][2]);
                red_add(a1 + 1, c[mt][nt][3]);
            }
        }

        grid_sync_dev();

        // ---------- phase B: one load, (s+eps)*po, deferred-norm belief, re-zero slab ----------
        {
            float s = __ldcg(&g_acc[bn*Sn + bj]);
            __stcg(&g_acc[bn*Sn + bj], 0.f);                // re-arm for next step
            float val = (s + EPSF) * __ldg(&g_po[((size_t)t*Bn + bn)*Sn + bj]);
            out_b[((size_t)t*Bn + bn)*Sn + bj] = val;       // unnormalized; fixed post-scan
            __stcg(&g_belT[(size_t)bj*Bn + bn], val);
            float ws = val;
            #pragma unroll
            for (int o = 16; o > 0; o >>= 1) ws += __shfl_xor_sync(0xffffffffu, ws, o);
            if (lane == 0) red[warp] = ws;
            __syncthreads();
            if (tid == 0) {
                float tot = 0.f;
                #pragma unroll
                for (int w = 0; w < 8; w++) tot += red[w];
                __stcg(&g_normAll[(t*2 + jh)*Bn + bn], tot);
            }
        }

        grid_sync_dev();
    }
}

// ---------------- post-scan: normalize out_b by per-(t,n) norms ----------------
__global__ void k_fix(float* __restrict__ out_b) {
    int tn = blockIdx.x;            // t*64 + n
    int t = tn >> 6, n = tn & 63;
    float inv = 1.f / (g_normAll[(t*2 + 0)*Bn + n] + g_normAll[(t*2 + 1)*Bn + n]);
    out_b[(size_t)tn*Sn + threadIdx.x] *= inv;
}

// ---------------- post-scan plan: tf32 MMA logits, softmax over A, tau-weighted sum ----------------
#define HB 4
#define AST 36    // padded strides: (4*gid + tig) mod 32 all-distinct -> bank-safe
__global__ void __launch_bounds__(256)
k_plan(const float* __restrict__ value,
       const float* __restrict__ alpha_b,
       float* __restrict__ out_pi) {
    int n  = blockIdx.x;
    int hq = blockIdx.y;          // 0..7, handles h = hq*HB .. +3
    int tid = threadIdx.x;        // 256
    int lane = tid & 31;
    int warp = tid >> 5;
    int h_l = warp & 3;           // h within group
    int mh  = warp >> 2;          // t-half (32 rows each)
    int gid = lane >> 2;
    int tig = lane & 3;

    __shared__ uint32_t Ash[64*AST];       // alpha_b tile, tf32  [t][i]
    __shared__ uint32_t Vsh[HB*16*AST];    // value tile,  tf32  [h][k][i]
    __shared__ float    Lsh[HB][64][17];

    float c[2][2][4];
    #pragma unroll
    for (int mt = 0; mt < 2; mt++)
        #pragma unroll
        for (int nt = 0; nt < 2; nt++)
            #pragma unroll
            for (int r = 0; r < 4; r++) c[mt][nt][r] = 0.f;

    for (int i0 = 0; i0 < Sn; i0 += 32) {
        #pragma unroll
        for (int q = 0; q < 8; q++) {                  // A: 64t x 32i
            int e = tid + q*256; int ii = e & 31, tt = e >> 5;
            Ash[tt*AST + ii] = f2tf32(alpha_b[((size_t)tt*Bn + n)*Sn + i0 + ii]);
        }
        #pragma unroll
        for (int q = 0; q < 8; q++) {                  // V: 4h x 16k x 32i
            int e = tid + q*256; int ii = e & 31, rest = e >> 5;
            int kk2 = rest & 15, hh = rest >> 4;
            Vsh[(hh*16 + kk2)*AST + ii] =
                f2tf32(value[(((size_t)(hq*HB + hh)*Bn + n)*An + kk2)*Sn + i0 + ii]);
        }
        __syncthreads();
        #pragma unroll
        for (int ksl = 0; ksl < 4; ksl++) {            // 4 k-steps of 8 i
            int ib = ksl*8;
            uint32_t a[2][4];
            #pragma unroll
            for (int mt = 0; mt < 2; mt++) {
                int tr = mh*32 + mt*16;
                a[mt][0] = Ash[(tr + gid    )*AST + ib + tig    ];
                a[mt][1] = Ash[(tr + gid + 8)*AST + ib + tig    ];
                a[mt][2] = Ash[(tr + gid    )*AST + ib + tig + 4];
                a[mt][3] = Ash[(tr + gid + 8)*AST + ib + tig + 4];
            }
            #pragma unroll
            for (int nt = 0; nt < 2; nt++) {
                uint32_t b0 = Vsh[(h_l*16 + nt*8 + gid)*AST + ib + tig    ];
                uint32_t b1 = Vsh[(h_l*16 + nt*8 + gid)*AST + ib + tig + 4];
                #pragma unroll
                for (int mt = 0; mt < 2; mt++)
                    mma_tf32(c[mt][nt][0], c[mt][nt][1], c[mt][nt][2], c[mt][nt][3],
                             a[mt][0], a[mt][1], a[mt][2], a[mt][3], b0, b1);
            }
        }
        __syncthreads();
    }

    // scatter logits to Lsh
    #pragma unroll
    for (int mt = 0; mt < 2; mt++)
        #pragma unroll
        for (int nt = 0; nt < 2; nt++) {
            int t0 = mh*32 + mt*16 + gid;
            int k0 = nt*8 + 2*tig;
            Lsh[h_l][t0    ][k0    ] = c[mt][nt][0];
            Lsh[h_l][t0    ][k0 + 1] = c[mt][nt][1];
            Lsh[h_l][t0 + 8][k0    ] = c[mt][nt][2];
            Lsh[h_l][t0 + 8][k0 + 1] = c[mt][nt][3];
        }
    __syncthreads();

    // 256 threads = 4h x 64t: softmax over 16 k + tau-weighted accumulate
    int hh = tid >> 6, t = tid & 63;
    float m = -1e30f;
    #pragma unroll
    for (int k = 0; k < An; k++) m = fmaxf(m, Lsh[hh][t][k]);
    float e[An]; float ssum = 0.f;
    #pragma unroll
    for (int k = 0; k < An; k++) { e[k] = expf(Lsh[hh][t][k] - m); ssum += e[k]; }
    float w = g_taupdf[hq*HB + hh] / ssum;
    #pragma unroll
    for (int k = 0; k < An; k++)
        atomicAdd(&out_pi[((size_t)t*Bn + n)*An + k], e[k] * w);
}

// ---------------- launch ----------------
extern "C" void kernel_launch(void* const* d_in, const int* in_sizes, int n_in,
                              void* d_out, int out_size) {
    const float* logp_o = (const float*)d_in[0];
    const float* logp_u = (const float*)d_in[1];
    const float* value  = (const float*)d_in[2];
    const float* b      = (const float*)d_in[3];
    const float* u      = (const float*)d_in[4];
    const float* v      = (const float*)d_in[5];
    const float* tau    = (const float*)d_in[6];

    float* out    = (float*)d_out;
    float* out_b  = out;                       // [T,B,S]
    float* out_pi = out + (size_t)Tn*Bn*Sn;    // [T,B,A]

    static int smem_set = 0;
    if (!smem_set) {
        cudaFuncSetAttribute(k_scan, cudaFuncAttributeMaxDynamicSharedMemorySize, SMEM_B);
        smem_set = 1;
    }

    k_pv<<<An, 64>>>(u, v);
    k_gram<<<Sn, 128>>>(u);
    k_trans16<<<dim3(Sn/16, An), 512>>>();
    k_taupdf<<<1, 32>>>(tau);
    k_alpha_a<<<(Tn*Bn + 127)/128, 128>>>(logp_u);
    k_po<<<(Tn*Bn*Sn)/512, 512>>>(logp_o);
    k_init_bel<<<Bn, Sn>>>(b);

    k_scan<<<NUNITS, 256, SMEM_B>>>(out_b);

    k_fix<<<Tn*Bn, Sn>>>(out_b);
    cudaMemsetAsync(out_pi, 0, sizeof(float)*(size_t)Tn*Bn*An);
    k_plan<<<dim3(Bn, Hn/HB), 256>>>(value, out_b, out_pi);
}

// round 12
// speedup vs baseline: 4.4611x; 1.3245x over previous
#include <cuda_runtime.h>
#include <cuda_fp16.h>
#include <math.h>
#include <stdint.h>

#define Tn 64
#define Bn 64
#define Sn 512
#define An 16
#define Rn 64
#define Hn 32
#define EPSF 1e-6f
#define BSCALE 4096.f

#define NUNITS 128       // persistent CTAs: one per 4-j chunk (all 16 k local)

// dynamic smem layout (bytes)
#define TSL_B    65536           // T slab: [32 ib][8 col8][32 lane][2 reg] fp16 = 64 KB
#define CSH_ROW4 65              // uint4 per belief row (512 halves + 8 pad)
#define CSH_B    (64*CSH_ROW4*16)    // 66560
#define AWSH_F   (64*17)
#define SMEM_TOT (TSL_B + CSH_B + AWSH_F*4 + 256*4 + 64*4)   // 137728

// ---------------- scratch (device globals; no allocation) ----------------
// T permuted: [jc(128)][ib(32)][col8(8)][lane(32)][reg(2)] halves, col = k*4 + (j&3)
__device__ __align__(16) unsigned short g_transPh[(size_t)An*Sn*Sn];  // 8.4 MB
__device__ float g_G[Sn*Sn];
__device__ float g_p[An*Sn];
__device__ float g_taupdf[Hn];
__device__ float g_alpha_a[(size_t)Tn*Bn*An];
__device__ __align__(16) __half g_belN[2*Bn*Sn];              // double-buffered belief [n][i], scaled x4096
__device__ __align__(16) float g_po[(size_t)Tn*Bn*Sn];        // exp(logp_o), 8 MB
__device__ __align__(16) float g_normP[(Tn+1)*Bn*8];          // per (t+1, n, slot) norm partials

__device__ int          g_bar_count;
__device__ volatile int g_bar_gen;

// ---------------- helpers ----------------
__device__ __forceinline__ uint32_t f2tf32(float x) {
    uint32_t u;
    asm("cvt.rna.tf32.f32 %0, %1;" : "=r"(u) : "f"(x));
    return u;
}

__device__ __forceinline__ void red_add(float* p, float v) {
    asm volatile("red.global.add.f32 [%0], %1;" :: "l"(p), "f"(v) : "memory");
}

__device__ __forceinline__ void mma_f16(float& c0, float& c1, float& c2, float& c3,
                                        uint32_t a0, uint32_t a1, uint32_t a2, uint32_t a3,
                                        uint32_t b0, uint32_t b1) {
    asm volatile("mma.sync.aligned.m16n8k16.row.col.f32.f16.f16.f32 "
                 "{%0,%1,%2,%3},{%4,%5,%6,%7},{%8,%9},{%0,%1,%2,%3};\n"
                 : "+f"(c0), "+f"(c1), "+f"(c2), "+f"(c3)
                 : "r"(a0), "r"(a1), "r"(a2), "r"(a3), "r"(b0), "r"(b1));
}

__device__ __forceinline__ void mma_tf32(float& c0, float& c1, float& c2, float& c3,
                                         uint32_t a0, uint32_t a1, uint32_t a2, uint32_t a3,
                                         uint32_t b0, uint32_t b1) {
    asm volatile("mma.sync.aligned.m16n8k8.row.col.f32.tf32.tf32.f32 "
                 "{%0,%1,%2,%3},{%4,%5,%6,%7},{%8,%9},{%0,%1,%2,%3};\n"
                 : "+f"(c0), "+f"(c1), "+f"(c2), "+f"(c3)
                 : "r"(a0), "r"(a1), "r"(a2), "r"(a3), "r"(b0), "r"(b1));
}

// ---------------- precompute: v_norm and p[k][i] = u[i].v_hat[k] ----------------
__global__ void k_pv(const float* __restrict__ u, const float* __restrict__ v) {
    int k = blockIdx.x;
    int t = threadIdx.x;  // 64
    __shared__ float vn[Rn];
    __shared__ float sb[64];
    float x = v[k*Rn + t];
    sb[t] = x * x;
    __syncthreads();
    for (int s = 32; s > 0; s >>= 1) { if (t < s) sb[t] += sb[t+s]; __syncthreads(); }
    vn[t] = x * rsqrtf(sb[0]);
    __syncthreads();
    for (int i = t; i < Sn; i += 64) {
        float s = 0.f;
        #pragma unroll
        for (int r = 0; r < Rn; r++) s += u[i*Rn + r] * vn[r];
        g_p[k*Sn + i] = s;
    }
}

// ---------------- precompute: G[i][j] = u[i].u[j] ----------------
__global__ void k_gram(const float* __restrict__ u) {
    int i = blockIdx.x;
    int tid = threadIdx.x;  // 128
    __shared__ float ui[Rn];
    if (tid < Rn) ui[tid] = u[i*Rn + tid];
    __syncthreads();
    for (int j = tid; j < Sn; j += 128) {
        float s = 0.f;
        #pragma unroll
        for (int r = 0; r < Rn; r++) s += u[j*Rn + r] * ui[r];
        g_G[i*Sn + j] = s;
    }
}

// ---------------- precompute: transition softmax -> j-chunk-sliced fp16 fragment layout ----------------
// block (ib, k): rows i = ib*16 + r; element (k,i,j) goes to slab jc=j>>2 at
// col = k*4 + (j&3): col8 = k>>1, c8 = (k&1)*4 + (j&3), lane = c8*4 + ((r&7)>>1), reg = r>>3, half = r&1
__global__ void k_trans16() {
    int ib = blockIdx.x, k = blockIdx.y;   // ib 0..31, k 0..15
    int j = threadIdx.x;  // 512
    __shared__ float red[512];
    __shared__ __align__(16) unsigned short stage[8192];  // [jc(128)][64]: run content for this (ib,k)
    float pkj = g_p[k*Sn + j];
    int jc = j >> 2, jj = j & 3;

    #pragma unroll 1
    for (int r = 0; r < 16; r++) {
        int i = ib*16 + r;
        float w = g_G[i*Sn + j] - 2.f * g_p[k*Sn + i] * pkj;
        red[j] = w; __syncthreads();
        for (int s = 256; s > 0; s >>= 1) { if (j < s) red[j] = fmaxf(red[j], red[j+s]); __syncthreads(); }
        float m = red[0]; __syncthreads();
        float e = expf(w - m);
        red[j] = e; __syncthreads();
        for (int s = 256; s > 0; s >>= 1) { if (j < s) red[j] += red[j+s]; __syncthreads(); }
        float pr = e * (1.f / red[0]);
        stage[jc*64 + jj*16 + ((r & 7) >> 1)*4 + (r >> 3)*2 + (r & 1)] =
            __half_as_ushort(__float2half_rn(pr));
        __syncthreads();
    }

    // coalesced writeout: 1024 uint4, each a half-run of a fragment block
    const uint4* s4 = reinterpret_cast<const uint4*>(stage);
    uint4* d4 = reinterpret_cast<uint4*>(g_transPh);
    #pragma unroll
    for (int q = 0; q < 2; q++) {
        int f = j + q*512;                 // 0..1023
        int jc2 = f >> 3, o = f & 7;
        size_t idx4 = ((size_t)(jc2*32 + ib)*8 + (k >> 1))*16 + (k & 1)*8 + o;
        d4[idx4] = s4[f];
    }
}

// ---------------- precompute: normalized Poisson pdf over horizon ----------------
__global__ void k_taupdf(const float* __restrict__ tau) {
    int t = threadIdx.x;  // 32
    float rate = log1pf(expf(tau[0]));
    float kk = (float)(t + 1);
    float lp = kk * logf(rate) - rate - lgammaf(kk + 1.f);
    float p = expf(lp);
    float s = p;
    #pragma unroll
    for (int o = 16; o > 0; o >>= 1) s += __shfl_xor_sync(0xffffffffu, s, o);
    g_taupdf[t] = p / s;
}

// ---------------- precompute: alpha_a = softmax(logp_u) over A ----------------
__global__ void k_alpha_a(const float* __restrict__ logp_u) {
    int idx = blockIdx.x * blockDim.x + threadIdx.x;
    if (idx >= Tn*Bn) return;
    const float* r = logp_u + (size_t)idx*An;
    float m = -1e30f;
    #pragma unroll
    for (int k = 0; k < An; k++) m = fmaxf(m, r[k]);
    float e[An]; float s = 0.f;
    #pragma unroll
    for (int k = 0; k < An; k++) { e[k] = expf(r[k] - m); s += e[k]; }
    float inv = 1.f / s;
    #pragma unroll
    for (int k = 0; k < An; k++) g_alpha_a[(size_t)idx*An + k] = e[k] * inv;
}

// ---------------- precompute: po = exp(logp_o); also zero the norm partials ----------------
__global__ void k_po(const float* __restrict__ logp_o) {
    size_t idx = (size_t)blockIdx.x * 512 + threadIdx.x;
    g_po[idx] = expf(logp_o[idx]);
    if (idx < (size_t)(Tn+1)*Bn*8) g_normP[idx] = 0.f;
}

// ---------------- init belief: fp16 rows [n][i], scaled; seed norm for t=0 ----------------
__global__ void k_init_bel(const float* __restrict__ b) {
    int n = blockIdx.x, j = threadIdx.x;  // (Bn, Sn)
    __shared__ float red[512];
    float bv = b[n*Sn + j] * BSCALE;
    g_belN[n*Sn + j] = __float2half_rn(bv);
    red[j] = bv; __syncthreads();
    for (int s = 256; s > 0; s >>= 1) { if (j < s) red[j] += red[j+s]; __syncthreads(); }
    if (j == 0) g_normP[n*8] = red[0];    // t=0 reads slot sums at index 0
}

// ---------------- grid-wide barrier (all NUNITS CTAs co-resident) ----------------
__device__ __forceinline__ void grid_sync_dev() {
    __syncthreads();
    if (threadIdx.x == 0) {
        int old = g_bar_gen;
        __threadfence();
        int t = atomicAdd(&g_bar_count, 1);
        if (t == NUNITS - 1) {
            g_bar_count = 0;
            __threadfence();
            g_bar_gen = old + 1;
        } else {
            while (g_bar_gen == old) __nanosleep(64);
        }
    }
    __syncthreads();
    __threadfence();
}

// ---------------- fused persistent scan: per-CTA j-chunk, all-k local, ONE barrier/step ----------------
__global__ void __launch_bounds__(256, 1)
k_scan(float* __restrict__ out_b) {
    extern __shared__ char smem[];
    uint4*          Tsl4 = reinterpret_cast<uint4*>(smem);
    const uint2*    Tsl2 = reinterpret_cast<const uint2*>(smem);
    char*           cshB = smem + TSL_B;
    uint4*          csh4 = reinterpret_cast<uint4*>(cshB);
    const uint32_t* csh2 = reinterpret_cast<const uint32_t*>(cshB);
    float* awsh  = reinterpret_cast<float*>(cshB + CSH_B);   // [64][17] raw alpha
    float* sacc  = awsh + AWSH_F;                            // [64][4]
    float* invsh = sacc + 256;                               // [64]

    int tid  = threadIdx.x;            // 256
    int jc   = blockIdx.x;             // 0..127 : j-chunk of 4
    int lane = tid & 31;
    int warp = tid >> 5;
    int gid  = lane >> 2;
    int tig  = lane & 3;
    int mw   = warp & 1;               // 2 warps over M (n)
    int nw   = warp >> 1;              // 4 warps over N (cols)
    int nwb  = mw * 32;
    int fn   = tid >> 2;               // final-phase n
    int fj   = tid & 3;                // final-phase jj
    int jj0  = (2*tig) & 3;

    // one-time: load this CTA's T slab (64 KB, contiguous)
    {
        const uint4* srcT = reinterpret_cast<const uint4*>(g_transPh) + (size_t)jc*4096;
        #pragma unroll
        for (int q = 0; q < 16; q++) Tsl4[tid + q*256] = srcT[tid + q*256];
    }
    __syncthreads();

    for (int t = 0; t < Tn; t++) {
        // prefetch po (off critical path), zero sacc, stage alpha + inv + belief
        float pof = __ldg(&g_po[((size_t)t*Bn + fn)*Sn + jc*4 + fj]);
        sacc[tid] = 0.f;
        #pragma unroll
        for (int q = 0; q < 4; q++) {
            int e = tid + q*256;                         // 0..1023
            awsh[(e >> 4)*17 + (e & 15)] =
                __ldg(&g_alpha_a[((size_t)t*Bn + (e >> 4))*An + (e & 15)]);
        }
        if (tid < Bn) {
            const float4* np = reinterpret_cast<const float4*>(&g_normP[(size_t)t*Bn*8 + tid*8]);
            float4 x = __ldcg(np), y = __ldcg(np + 1);
            invsh[tid] = 1.f / (x.x + x.y + x.z + x.w + y.x + y.y + y.z + y.w);
        }
        {
            const uint4* belc = reinterpret_cast<const uint4*>(g_belN + (size_t)(t & 1)*Bn*Sn);
            #pragma unroll
            for (int q = 0; q < 16; q++) {
                int f = tid + q*256;                     // 0..4095
                csh4[(f >> 6)*CSH_ROW4 + (f & 63)] = __ldcg(&belc[f]);
            }
        }
        __syncthreads();

        // GEMM: M[n, col] = sum_i bel[n,i] * T[i, col], col = k*4+jj (64 cols)
        float c[2][2][4];
        #pragma unroll
        for (int mt = 0; mt < 2; mt++)
            #pragma unroll
            for (int nt = 0; nt < 2; nt++)
                #pragma unroll
                for (int r = 0; r < 4; r++) c[mt][nt][r] = 0.f;

        #pragma unroll 8
        for (int ks = 0; ks < 32; ks++) {
            uint32_t a[2][4];
            #pragma unroll
            for (int mt = 0; mt < 2; mt++) {
                int rb = (nwb + mt*16 + gid)*260 + ks*8 + tig;
                a[mt][0] = csh2[rb];
                a[mt][1] = csh2[rb + 8*260];
                a[mt][2] = csh2[rb + 4];
                a[mt][3] = csh2[rb + 8*260 + 4];
            }
            #pragma unroll
            for (int nt = 0; nt < 2; nt++) {
                uint2 bf = Tsl2[(ks*8 + nw*2 + nt)*32 + lane];
                #pragma unroll
                for (int mt = 0; mt < 2; mt++)
                    mma_f16(c[mt][nt][0], c[mt][nt][1], c[mt][nt][2], c[mt][nt][3],
                            a[mt][0], a[mt][1], a[mt][2], a[mt][3], bf.x, bf.y);
            }
        }

        // epilogue: local k-sum with raw alpha weights -> SMEM atomics
        #pragma unroll
        for (int mt = 0; mt < 2; mt++) {
            int n_a = nwb + mt*16 + gid;
            float pa0 = 0.f, pa1 = 0.f, pb0 = 0.f, pb1 = 0.f;
            #pragma unroll
            for (int nt = 0; nt < 2; nt++) {
                int k = nw*4 + nt*2 + (tig >> 1);
                float wA = awsh[n_a*17 + k];
                float wB = awsh[(n_a + 8)*17 + k];
                pa0 += wA * c[mt][nt][0]; pa1 += wA * c[mt][nt][1];
                pb0 += wB * c[mt][nt][2]; pb1 += wB * c[mt][nt][3];
            }
            atomicAdd(&sacc[n_a*4 + jj0],           pa0);
            atomicAdd(&sacc[n_a*4 + jj0 + 1],       pa1);
            atomicAdd(&sacc[(n_a + 8)*4 + jj0],     pb0);
            atomicAdd(&sacc[(n_a + 8)*4 + jj0 + 1], pb1);
        }
        __syncthreads();

        // finalize: val = (s_norm + eps)*po ; write belief (x4096 fp16), out_b, norm REDs
        {
            float val = (sacc[tid] * invsh[fn] + EPSF) * pof;
            float vs  = val * BSCALE;
            out_b[((size_t)t*Bn + fn)*Sn + jc*4 + fj] = vs;   // unnormalized; fixed post-scan
            unsigned short us = __half_as_ushort(__float2half_rn(vs));
            unsigned short* bp = reinterpret_cast<unsigned short*>(
                g_belN + (size_t)((t + 1) & 1)*Bn*Sn) + fn*Sn + jc*4 + fj;
            asm volatile("st.global.cg.u16 [%0], %1;" :: "l"(bp), "h"(us) : "memory");
            float w = vs;
            w += __shfl_xor_sync(0xffffffffu, w, 1);
            w += __shfl_xor_sync(0xffffffffu, w, 2);
            if ((lane & 3) == 0)
                red_add(&g_normP[(size_t)(t + 1)*Bn*8 + fn*8 + (jc & 7)], w);
        }

        grid_sync_dev();
    }
}

// ---------------- post-scan: normalize out_b by per-(t,n) norms ----------------
__global__ void k_fix(float* __restrict__ out_b) {
    int tn = blockIdx.x;            // t*64 + n
    int t = tn >> 6, n = tn & 63;
    __shared__ float inv;
    if (threadIdx.x == 0) {
        const float* np = &g_normP[(size_t)(t + 1)*Bn*8 + n*8];
        float s = np[0] + np[1] + np[2] + np[3] + np[4] + np[5] + np[6] + np[7];
        inv = 1.f / s;
    }
    __syncthreads();
    out_b[(size_t)tn*Sn + threadIdx.x] *= inv;
}

// ---------------- post-scan plan: tf32 MMA logits, softmax over A, tau-weighted sum ----------------
#define HB 4
#define AST 36
__global__ void __launch_bounds__(256)
k_plan(const float* __restrict__ value,
       const float* __restrict__ alpha_b,
       float* __restrict__ out_pi) {
    int n  = blockIdx.x;
    int hq = blockIdx.y;
    int tid = threadIdx.x;
    int lane = tid & 31;
    int warp = tid >> 5;
    int h_l = warp & 3;
    int mh  = warp >> 2;
    int gid = lane >> 2;
    int tig = lane & 3;

    __shared__ uint32_t Ash[64*AST];
    __shared__ uint32_t Vsh[HB*16*AST];
    __shared__ float    Lsh[HB][64][17];

    float c[2][2][4];
    #pragma unroll
    for (int mt = 0; mt < 2; mt++)
        #pragma unroll
        for (int nt = 0; nt < 2; nt++)
            #pragma unroll
            for (int r = 0; r < 4; r++) c[mt][nt][r] = 0.f;

    for (int i0 = 0; i0 < Sn; i0 += 32) {
        #pragma unroll
        for (int q = 0; q < 8; q++) {
            int e = tid + q*256; int ii = e & 31, tt = e >> 5;
            Ash[tt*AST + ii] = f2tf32(alpha_b[((size_t)tt*Bn + n)*Sn + i0 + ii]);
        }
        #pragma unroll
        for (int q = 0; q < 8; q++) {
            int e = tid + q*256; int ii = e & 31, rest = e >> 5;
            int kk2 = rest & 15, hh = rest >> 4;
            Vsh[(hh*16 + kk2)*AST + ii] =
                f2tf32(value[(((size_t)(hq*HB + hh)*Bn + n)*An + kk2)*Sn + i0 + ii]);
        }
        __syncthreads();
        #pragma unroll
        for (int ksl = 0; ksl < 4; ksl++) {
            int ib = ksl*8;
            uint32_t a[2][4];
            #pragma unroll
            for (int mt = 0; mt < 2; mt++) {
                int tr = mh*32 + mt*16;
                a[mt][0] = Ash[(tr + gid    )*AST + ib + tig    ];
                a[mt][1] = Ash[(tr + gid + 8)*AST + ib + tig    ];
                a[mt][2] = Ash[(tr + gid    )*AST + ib + tig + 4];
                a[mt][3] = Ash[(tr + gid + 8)*AST + ib + tig + 4];
            }
            #pragma unroll
            for (int nt = 0; nt < 2; nt++) {
                uint32_t b0 = Vsh[(h_l*16 + nt*8 + gid)*AST + ib + tig    ];
                uint32_t b1 = Vsh[(h_l*16 + nt*8 + gid)*AST + ib + tig + 4];
                #pragma unroll
                for (int mt = 0; mt < 2; mt++)
                    mma_tf32(c[mt][nt][0], c[mt][nt][1], c[mt][nt][2], c[mt][nt][3],
                             a[mt][0], a[mt][1], a[mt][2], a[mt][3], b0, b1);
            }
        }
        __syncthreads();
    }

    #pragma unroll
    for (int mt = 0; mt < 2; mt++)
        #pragma unroll
        for (int nt = 0; nt < 2; nt++) {
            int t0 = mh*32 + mt*16 + gid;
            int k0 = nt*8 + 2*tig;
            Lsh[h_l][t0    ][k0    ] = c[mt][nt][0];
            Lsh[h_l][t0    ][k0 + 1] = c[mt][nt][1];
            Lsh[h_l][t0 + 8][k0    ] = c[mt][nt][2];
            Lsh[h_l][t0 + 8][k0 + 1] = c[mt][nt][3];
        }
    __syncthreads();

    int hh = tid >> 6, t = tid & 63;
    float m = -1e30f;
    #pragma unroll
    for (int k = 0; k < An; k++) m = fmaxf(m, Lsh[hh][t][k]);
    float e[An]; float ssum = 0.f;
    #pragma unroll
    for (int k = 0; k < An; k++) { e[k] = expf(Lsh[hh][t][k] - m); ssum += e[k]; }
    float w = g_taupdf[hq*HB + hh] / ssum;
    #pragma unroll
    for (int k = 0; k < An; k++)
        atomicAdd(&out_pi[((size_t)t*Bn + n)*An + k], e[k] * w);
}

// ---------------- launch ----------------
extern "C" void kernel_launch(void* const* d_in, const int* in_sizes, int n_in,
                              void* d_out, int out_size) {
    const float* logp_o = (const float*)d_in[0];
    const float* logp_u = (const float*)d_in[1];
    const float* value  = (const float*)d_in[2];
    const float* b      = (const float*)d_in[3];
    const float* u      = (const float*)d_in[4];
    const float* v      = (const float*)d_in[5];
    const float* tau    = (const float*)d_in[6];

    float* out    = (float*)d_out;
    float* out_b  = out;                       // [T,B,S]
    float* out_pi = out + (size_t)Tn*Bn*Sn;    // [T,B,A]

    static int smem_set = 0;
    if (!smem_set) {
        cudaFuncSetAttribute(k_scan, cudaFuncAttributeMaxDynamicSharedMemorySize, SMEM_TOT);
        smem_set = 1;
    }

    k_pv<<<An, 64>>>(u, v);
    k_gram<<<Sn, 128>>>(u);
    k_trans16<<<dim3(Sn/16, An), 512>>>();
    k_taupdf<<<1, 32>>>(tau);
    k_alpha_a<<<(Tn*Bn + 127)/128, 128>>>(logp_u);
    k_po<<<(Tn*Bn*Sn)/512, 512>>>(logp_o);     // also zeroes g_normP
    k_init_bel<<<Bn, Sn>>>(b);                 // writes buf0 + t=0 norm seed

    k_scan<<<NUNITS, 256, SMEM_TOT>>>(out_b);

    k_fix<<<Tn*Bn, Sn>>>(out_b);
    cudaMemsetAsync(out_pi, 0, sizeof(float)*(size_t)Tn*Bn*An);
    k_plan<<<dim3(Bn, Hn/HB), 256>>>(value, out_b, out_pi);
}